// round 14
// baseline (speedup 1.0000x reference)
#include <cuda_runtime.h>
#include <cstdint>

#define NG    1000
#define NODES 100
#define EDGES 1600
#define NTOT  100000
#define ETOT  1600000
#define HID   128
#define KTOP  40
#define HALF  500
#define MH    (HALF * NODES)

// ---------------- scratch (device globals; no runtime allocation) ----------
__device__ float g_X0 [(size_t)NTOT * HID];
__device__ float g_X1 [(size_t)NTOT * HID];
__device__ float g_X2 [(size_t)NTOT * HID];
__device__ float g_ZW [1000 * HID];
__device__ float g_Wh [1024 * 128];
__device__ float g_Wl [1024 * 128];
__device__ float g_flat[(size_t)NG * 512];
__device__ float g_P  [(size_t)NG * 128];
__device__ int   g_off [NG * 101];
__device__ int2  g_edge[ETOT];

// ---------------- helpers ---------------------------------------------------
__device__ __forceinline__ float acc_tanh(float x) {
    float xc = fminf(fmaxf(x, -10.f), 10.f);
    float e  = __expf(2.f * xc);
    return (e - 1.f) / (e + 1.f);
}
__device__ __forceinline__ float f2tf32f(float x) {
    uint32_t r;
    asm("cvt.rna.tf32.f32 %0, %1;" : "=r"(r) : "f"(x));
    return __uint_as_float(r);
}
__device__ __forceinline__ void mma_tf32(float c[4], const uint32_t a[4],
                                         const uint32_t b0, const uint32_t b1) {
    asm volatile(
        "mma.sync.aligned.m16n8k8.row.col.f32.tf32.tf32.f32 "
        "{%0,%1,%2,%3}, {%4,%5,%6,%7}, {%8,%9}, {%0,%1,%2,%3};\n"
        : "+f"(c[0]), "+f"(c[1]), "+f"(c[2]), "+f"(c[3])
        : "r"(a[0]), "r"(a[1]), "r"(a[2]), "r"(a[3]), "r"(b0), "r"(b1));
}
__device__ __forceinline__ uint32_t smem_u32(const void* p) {
    return (uint32_t)__cvta_generic_to_shared(p);
}
#define CP16(dst, src) \
    asm volatile("cp.async.cg.shared.global [%0], [%1], 16;\n" :: "r"(dst), "l"(src))
#define CPCOMMIT() asm volatile("cp.async.commit_group;\n" ::: "memory")
#define CPWAIT2()  asm volatile("cp.async.wait_group 2;\n" ::: "memory")
#define CPWAIT1()  asm volatile("cp.async.wait_group 1;\n" ::: "memory")

__device__ __forceinline__ unsigned long long pkf2(float a, float b) {
    unsigned long long r;
    asm("mov.b64 %0, {%1, %2};" : "=l"(r) : "r"(__float_as_int(a)), "r"(__float_as_int(b)));
    return r;
}
__device__ __forceinline__ void ffma2(unsigned long long& d,
                                      unsigned long long a, unsigned long long b) {
    asm("fma.rn.f32x2 %0, %1, %2, %3;" : "=l"(d) : "l"(a), "l"(b), "l"(d));
}
__device__ __forceinline__ float hsum2(unsigned long long u) {
    int lo, hi;
    asm("mov.b64 {%0, %1}, %2;" : "=r"(lo), "=r"(hi) : "l"(u));
    return __int_as_float(lo) + __int_as_float(hi);
}

// ---------------- prep: pre-split weights into hi/lo ------------------------
// rows [0,128)=W0_top, [128,256)=W0_bot, [256,384)=W1, [384,512)=W2, [512,1024)=mW1
__global__ void __launch_bounds__(256) prep_gcn(
    const float* __restrict__ W0, const float* __restrict__ W1,
    const float* __restrict__ W2)
{
    int t = blockIdx.x * 256 + threadIdx.x;
    if (t >= 512 * 128) return;
    int row = t >> 7, col = t & 127;
    float v;
    if (row < 256)      v = W0[row * 128 + col];
    else if (row < 384) v = W1[(row - 256) * 128 + col];
    else                v = W2[(row - 384) * 128 + col];
    float h = f2tf32f(v);
    g_Wh[t] = h;
    g_Wl[t] = v - h;
}
__global__ void __launch_bounds__(256) prep_mlp(const float* __restrict__ mW1)
{
    int t = blockIdx.x * 256 + threadIdx.x;
    if (t >= 512 * 128) return;
    float v = mW1[t];
    float h = f2tf32f(v);
    g_Wh[512 * 128 + t] = h;
    g_Wl[512 * 128 + t] = v - h;
}

// ---------------- one-pass deterministic CSR --------------------------------
__global__ void __launch_bounds__(256) build_csr(const int* __restrict__ ei, int g0)
{
    __shared__ int2  sedge[EDGES];
    __shared__ int   hist [8][104];
    __shared__ int   cbase[8][104];
    __shared__ int   deg  [NODES];
    __shared__ float dinv [NODES];
    __shared__ int   offs [NODES + 1];

    const int g = g0 + blockIdx.x, tid = threadIdx.x;
    const int lane = tid & 31, warp = tid >> 5;
    const int base = g * NODES;
    const int* srce = ei + (size_t)g * EDGES;
    const int* dste = ei + (size_t)ETOT + (size_t)g * EDGES;

    for (int t = tid; t < 8 * 104; t += 256) ((int*)hist)[t] = 0;
    for (int e = tid; e < EDGES; e += 256)
        sedge[e] = make_int2(srce[e] - base, dste[e] - base);
    __syncthreads();

    const int cbeg = warp * 200;
    for (int j = lane; j < 200; j += 32)
        atomicAdd(&hist[warp][sedge[cbeg + j].y], 1);
    __syncthreads();

    if (tid < NODES) {
        int s = 0;
#pragma unroll
        for (int w = 0; w < 8; w++) s += hist[w][tid];
        deg[tid] = s;
        dinv[tid] = s > 0 ? rsqrtf((float)s) : 0.f;
    }
    __syncthreads();
    if (tid == 0) {
        int acc = 0;
        for (int i = 0; i < NODES; i++) { offs[i] = acc; acc += deg[i]; }
        offs[NODES] = acc;
    }
    __syncthreads();
    if (tid < NODES) {
        int run = offs[tid];
#pragma unroll
        for (int w = 0; w < 8; w++) {
            cbase[w][tid] = run;
            run += hist[w][tid];
            hist[w][tid] = 0;
        }
    }
    if (tid <= NODES) g_off[g * 101 + tid] = offs[tid];
    __syncthreads();

    const size_t gb = (size_t)g * EDGES;
    for (int j0 = 0; j0 < 200; j0 += 32) {
        int j = j0 + lane;
        bool act = j < 200;
        unsigned amask = __ballot_sync(0xffffffffu, act);
        if (act) {
            int2 sd = sedge[cbeg + j];
            unsigned mm = __match_any_sync(amask, sd.y);
            unsigned below = mm & ((1u << lane) - 1);
            int c = hist[warp][sd.y];
            __syncwarp(amask);
            g_edge[gb + cbase[warp][sd.y] + c + __popc(below)] =
                make_int2(sd.x, __float_as_int(dinv[sd.x] * dinv[sd.y]));
            if (below == 0)
                hist[warp][sd.y] = c + __popc(mm);
        }
        __syncwarp();
    }
}

// ---------------- fused layer: GEMM (3xTF32) + agg + tanh, 1 CTA per graph --
// T kept in SMEM; edges prefetched via cp.async group 0.
#define FL_ASL 1024          // 128 rows * 8 (rows >=100 unwritten, discarded)
#define FL_BSL 2112          // Bh 8*132 + Bl 8*132
#define FUSED_SMEM ((3 * FL_ASL + 3 * FL_BSL + 100 * 132 + EDGES * 2 + 104) * 4)

template <int ZADD>
__global__ void __launch_bounds__(256, 2) fused_layer(
    const float* __restrict__ Aa, const int* __restrict__ z,
    const float* __restrict__ ZW,
    const float* __restrict__ Wh, const float* __restrict__ Wl,
    const float* __restrict__ bias, float* __restrict__ Xout, int g0)
{
    extern __shared__ float sm[];
    float* As   = sm;                       // 3*1024
    float* Bs   = As + 3 * FL_ASL;          // 3*2112
    float* Ts   = Bs + 3 * FL_BSL;          // 100*132
    int2*  sed  = (int2*)(Ts + 100 * 132);  // 1600
    int*   soff = (int*)(sed + EDGES);      // 104

    const int g = g0 + blockIdx.x, tid = threadIdx.x;
    const int lane = tid & 31, wid = tid >> 5;
    const int wm = wid & 1, wn = wid >> 1;
    const int l4 = lane >> 2, lm = lane & 3;

    const int arow = tid >> 1, ahalf = (tid & 1) * 4;   // valid for tid<200
    const int bk = tid >> 5, bn4 = (tid & 31) * 4;

    const float* aptr  = Aa + ((size_t)g * NODES + arow) * HID;
    const float* bptrH = Wh + (size_t)bk * HID + bn4;
    const float* bptrL = Wl + (size_t)bk * HID + bn4;
    const uint32_t adst = smem_u32(As + arow * 8 + ahalf);
    const uint32_t bdst = smem_u32(Bs + bk * 132 + bn4);

    // --- group 0: prefetch edge list (hidden under mma pipeline) ------------
    {
        const int4* egi = (const int4*)(g_edge + (size_t)g * EDGES);
        const uint32_t sdst = smem_u32(sed);
        for (int t = tid; t < EDGES / 2; t += 256)
            CP16(sdst + t * 16, egi + t);
        CPCOMMIT();
    }

    auto issue = [&](int s) {
        const int buf = s % 3;
        if (tid < 200)
            CP16(adst + buf * (FL_ASL * 4), aptr + s * 8 + ahalf);
        CP16(bdst + buf * (FL_BSL * 4), bptrH + (size_t)s * 8 * HID);
        CP16(bdst + buf * (FL_BSL * 4) + 4224, bptrL + (size_t)s * 8 * HID);
        CPCOMMIT();
    };

    float acc[4][4][4];
#pragma unroll
    for (int mi = 0; mi < 4; mi++)
#pragma unroll
        for (int nj = 0; nj < 4; nj++)
#pragma unroll
            for (int q = 0; q < 4; q++) acc[mi][nj][q] = 0.f;

    issue(0); issue(1);

    // offsets (regular loads; latency hidden behind pipeline)
    if (tid <= NODES) soff[tid] = g_off[g * 101 + tid];

#pragma unroll 1
    for (int s = 0; s < 16; s++) {
        CPWAIT1();
        __syncthreads();
        if (s + 2 < 16) issue(s + 2);

        const float* A0  = As + (s % 3) * FL_ASL;
        const float* B0h = Bs + (s % 3) * FL_BSL;
        const float* B0l = B0h + 1056;

        uint32_t bh[4][2], bl[4][2];
#pragma unroll
        for (int nj = 0; nj < 4; nj++) {
            int n = wn * 32 + nj * 8 + l4;
            bh[nj][0] = __float_as_uint(B0h[lm * 132 + n]);
            bh[nj][1] = __float_as_uint(B0h[(lm + 4) * 132 + n]);
            bl[nj][0] = __float_as_uint(B0l[lm * 132 + n]);
            bl[nj][1] = __float_as_uint(B0l[(lm + 4) * 132 + n]);
        }
#pragma unroll
        for (int mi = 0; mi < 4; mi++) {
            int r = (wm * 4 + mi) * 16 + l4;
            float r0 = A0[r * 8 + lm];
            float r1 = A0[(r + 8) * 8 + lm];
            float r2 = A0[r * 8 + lm + 4];
            float r3 = A0[(r + 8) * 8 + lm + 4];
            float h0 = f2tf32f(r0), h1 = f2tf32f(r1);
            float h2 = f2tf32f(r2), h3 = f2tf32f(r3);
            uint32_t ah[4] = { __float_as_uint(h0), __float_as_uint(h1),
                               __float_as_uint(h2), __float_as_uint(h3) };
            uint32_t al[4] = { __float_as_uint(r0 - h0), __float_as_uint(r1 - h1),
                               __float_as_uint(r2 - h2), __float_as_uint(r3 - h3) };
#pragma unroll
            for (int nj = 0; nj < 4; nj++) {
                mma_tf32(acc[mi][nj], ah, bh[nj][0], bh[nj][1]);
                mma_tf32(acc[mi][nj], ah, bl[nj][0], bl[nj][1]);
                mma_tf32(acc[mi][nj], al, bh[nj][0], bh[nj][1]);
            }
        }
        __syncthreads();
    }

    // --- epilogue: T -> SMEM (stride 132), + ZW[z] for layer 0 ---------------
#pragma unroll
    for (int mi = 0; mi < 4; mi++) {
        int r = wm * 64 + mi * 16 + l4;
        const float* zw0 = nullptr;
        const float* zw1 = nullptr;
        if (ZADD) {
            zw0 = ZW + (size_t)((r     < NODES) ? z[(size_t)g * NODES + r]     : 0) * HID;
            zw1 = ZW + (size_t)((r + 8 < NODES) ? z[(size_t)g * NODES + r + 8] : 0) * HID;
        }
#pragma unroll
        for (int nj = 0; nj < 4; nj++) {
            int c = wn * 32 + nj * 8 + 2 * lm;
            float v0 = acc[mi][nj][0], v1 = acc[mi][nj][1];
            float v2 = acc[mi][nj][2], v3 = acc[mi][nj][3];
            if (ZADD) {
                v0 += zw0[c]; v1 += zw0[c + 1];
                v2 += zw1[c]; v3 += zw1[c + 1];
            }
            if (r < NODES)
                *(float2*)&Ts[r * 132 + c] = make_float2(v0, v1);
            if (r + 8 < NODES)
                *(float2*)&Ts[(r + 8) * 132 + c] = make_float2(v2, v3);
        }
    }
    asm volatile("cp.async.wait_group 0;\n" ::: "memory");  // edges ready
    __syncthreads();

    // --- aggregation + tanh from SMEM T --------------------------------------
    const float4 bv = *(const float4*)(bias + lane * 4);
    for (int d = wid; d < NODES; d += 8) {
        int e0 = soff[d], e1 = soff[d + 1];
        float4 a4 = make_float4(0.f, 0.f, 0.f, 0.f);
        if (e0 < e1) {
            int2 p0 = sed[e0];
            float4 t0 = *(const float4*)&Ts[p0.x * 132 + lane * 4];
#pragma unroll 2
            for (int e = e0 + 1; e < e1; e++) {
                int2 p1 = sed[e];
                float4 t1 = *(const float4*)&Ts[p1.x * 132 + lane * 4];
                float w = __int_as_float(p0.y);
                a4.x += w * t0.x; a4.y += w * t0.y;
                a4.z += w * t0.z; a4.w += w * t0.w;
                p0 = p1; t0 = t1;
            }
            float w = __int_as_float(p0.y);
            a4.x += w * t0.x; a4.y += w * t0.y;
            a4.z += w * t0.z; a4.w += w * t0.w;
        }
        float4 o;
        o.x = acc_tanh(a4.x + bv.x);
        o.y = acc_tanh(a4.y + bv.y);
        o.z = acc_tanh(a4.z + bv.z);
        o.w = acc_tanh(a4.w + bv.w);
        *(float4*)(Xout + ((size_t)g * NODES + d) * HID + lane * 4) = o;
    }
}

// ---------------- generic tensor-core GEMM (ZW prep + mlp1) ------------------
#define B_SLICE 2112
#define A_SLICE 1024
#define GEMM_SM ((4 * A_SLICE + 4 * B_SLICE) * 4)

template <int K, int RELU>
__global__ void __launch_bounds__(256, 2) gemm_tc(
    const float* __restrict__ Aa,
    const float* __restrict__ Wh, const float* __restrict__ Wl,
    const float* __restrict__ bias, float* __restrict__ C, int M)
{
    extern __shared__ float sm[];
    float* As = sm;
    float* Bs = sm + 4 * A_SLICE;

    const int tid = threadIdx.x;
    const int lane = tid & 31, wid = tid >> 5;
    const int wm = wid & 1, wn = wid >> 1;
    const int l4 = lane >> 2, lm = lane & 3;
    const int row0 = blockIdx.x * 128;

    const int arow = tid >> 1, ahalf = (tid & 1) * 4;
    const int bk = tid >> 5, bn4 = (tid & 31) * 4;

    const int gr = row0 + arow;
    const int grc = gr < M ? gr : (M - 1);
    const float* aptr = Aa + (size_t)grc * K;
    const float* bptrH = Wh + (size_t)bk * HID + bn4;
    const float* bptrL = Wl + (size_t)bk * HID + bn4;
    const uint32_t adst = smem_u32(As + arow * 8 + ahalf);
    const uint32_t bdst = smem_u32(Bs + bk * 132 + bn4);

    const int S = K / 8;

    auto issue = [&](int s) {
        const int buf = s & 3;
        CP16(adst + buf * (A_SLICE * 4), aptr + s * 8 + ahalf);
        CP16(bdst + buf * (B_SLICE * 4), bptrH + (size_t)s * 8 * HID);
        CP16(bdst + buf * (B_SLICE * 4) + 4224, bptrL + (size_t)s * 8 * HID);
        CPCOMMIT();
    };

    float acc[4][4][4];
#pragma unroll
    for (int mi = 0; mi < 4; mi++)
#pragma unroll
        for (int nj = 0; nj < 4; nj++)
#pragma unroll
            for (int q = 0; q < 4; q++) acc[mi][nj][q] = 0.f;

    issue(0); issue(1); issue(2);

#pragma unroll 1
    for (int s = 0; s < S; s++) {
        CPWAIT2();
        __syncthreads();
        if (s + 3 < S) issue(s + 3);

        const float* A0  = As + (s & 3) * A_SLICE;
        const float* B0h = Bs + (s & 3) * B_SLICE;
        const float* B0l = B0h + 1056;

        uint32_t bh[4][2], bl[4][2];
#pragma unroll
        for (int nj = 0; nj < 4; nj++) {
            int n = wn * 32 + nj * 8 + l4;
            bh[nj][0] = __float_as_uint(B0h[lm * 132 + n]);
            bh[nj][1] = __float_as_uint(B0h[(lm + 4) * 132 + n]);
            bl[nj][0] = __float_as_uint(B0l[lm * 132 + n]);
            bl[nj][1] = __float_as_uint(B0l[(lm + 4) * 132 + n]);
        }
#pragma unroll
        for (int mi = 0; mi < 4; mi++) {
            int r = (wm * 4 + mi) * 16 + l4;
            float r0 = A0[r * 8 + lm];
            float r1 = A0[(r + 8) * 8 + lm];
            float r2 = A0[r * 8 + lm + 4];
            float r3 = A0[(r + 8) * 8 + lm + 4];
            float h0 = f2tf32f(r0), h1 = f2tf32f(r1);
            float h2 = f2tf32f(r2), h3 = f2tf32f(r3);
            uint32_t ah[4] = { __float_as_uint(h0), __float_as_uint(h1),
                               __float_as_uint(h2), __float_as_uint(h3) };
            uint32_t al[4] = { __float_as_uint(r0 - h0), __float_as_uint(r1 - h1),
                               __float_as_uint(r2 - h2), __float_as_uint(r3 - h3) };
#pragma unroll
            for (int nj = 0; nj < 4; nj++) {
                mma_tf32(acc[mi][nj], ah, bh[nj][0], bh[nj][1]);
                mma_tf32(acc[mi][nj], ah, bl[nj][0], bl[nj][1]);
                mma_tf32(acc[mi][nj], al, bh[nj][0], bh[nj][1]);
            }
        }
        __syncthreads();
    }

#pragma unroll
    for (int mi = 0; mi < 4; mi++) {
#pragma unroll
        for (int nj = 0; nj < 4; nj++) {
            int r = row0 + wm * 64 + mi * 16 + l4;
            int c = wn * 32 + nj * 8 + 2 * lm;
            float v0 = acc[mi][nj][0], v1 = acc[mi][nj][1];
            float v2 = acc[mi][nj][2], v3 = acc[mi][nj][3];
            if (RELU) {
                float b0v = bias[c], b1v = bias[c + 1];
                v0 = fmaxf(v0 + b0v, 0.f); v1 = fmaxf(v1 + b1v, 0.f);
                v2 = fmaxf(v2 + b0v, 0.f); v3 = fmaxf(v3 + b1v, 0.f);
            }
            if (r < M)
                *(float2*)(C + (size_t)r * HID + c) = make_float2(v0, v1);
            if (r + 8 < M)
                *(float2*)(C + (size_t)(r + 8) * HID + c) = make_float2(v2, v3);
        }
    }
}

// ---------------- final part 1: layer3 + sort-pool + conv1/2 -> flat --------
#define FEAT_SMEM_FLOATS 25616
__global__ void __launch_bounds__(256) final_feat(
    const float* __restrict__ W3,  const float* __restrict__ b3,
    const float* __restrict__ cw1, const float* __restrict__ cb1,
    const float* __restrict__ cw2, const float* __restrict__ cb2, int g0)
{
    extern __shared__ float sm[];
    float* W3s  = sm;
    float* cw1s = W3s + 128;
    float* cw2s = cw1s + 6208;
    float* feat = cw2s + 2560;
    float* t3   = feat + 15520;
    float* x3   = t3 + 100;
    float* y1   = x3 + 100;
    float* mmp  = y1 + 640;
    int*   topi = (int*)(mmp + 320);

    const int g = g0 + blockIdx.x, tid = threadIdx.x;
    const float* X2g = g_X2 + (size_t)g * NODES * HID;

    if (tid < 128) W3s[tid] = W3[tid];
    for (int t = tid; t < 16 * 385; t += 256) {
        int c = t / 385, d = t - c * 385;
        cw1s[c * 388 + d] = cw1[t];
    }
    if (tid < 16) {
        cw1s[tid * 388 + 385] = 0.f;
        cw1s[tid * 388 + 386] = 0.f;
        cw1s[tid * 388 + 387] = 0.f;
    }
    for (int t = tid; t < 2560; t += 256) cw2s[t] = cw2[t];
    __syncthreads();

    if (tid < NODES) {
        const float4* xr = (const float4*)(X2g + (size_t)tid * HID);
        const float4* wr = (const float4*)W3s;
        float a = 0.f;
#pragma unroll 8
        for (int k = 0; k < 32; k++) {
            float4 xv = xr[k], wv = wr[k];
            a += xv.x * wv.x + xv.y * wv.y + xv.z * wv.z + xv.w * wv.w;
        }
        t3[tid] = a;
    }
    __syncthreads();

    if (tid < NODES) {
        const int*  offp = g_off + g * 101;
        const int2* ep   = g_edge + (size_t)g * EDGES;
        float a = 0.f;
        int e1 = offp[tid + 1];
        for (int e = offp[tid]; e < e1; e++) {
            int2 pe = ep[e];
            a += __int_as_float(pe.y) * t3[pe.x];
        }
        x3[tid] = acc_tanh(a + b3[0]);
    }
    __syncthreads();

    if (tid < NODES) {
        float v = x3[tid];
        int r = 0;
        for (int j = 0; j < NODES; j++) {
            float u = x3[j];
            r += (u > v) || (u == v && j < tid);
        }
        if (r < KTOP) topi[r] = tid;
    }
    __syncthreads();

    for (int t = tid; t < KTOP * HID; t += 256) {
        int k = t >> 7, d = t & 127;
        int node = topi[k];
        size_t gbase = ((size_t)g * NODES + node) * HID + d;
        feat[k * 388 + d]       = g_X0[gbase];
        feat[k * 388 + 128 + d] = g_X1[gbase];
        feat[k * 388 + 256 + d] = g_X2[gbase];
    }
    if (tid < KTOP) {
        feat[tid * 388 + 384] = x3[topi[tid]];
        feat[tid * 388 + 385] = 0.f;
        feat[tid * 388 + 386] = 0.f;
        feat[tid * 388 + 387] = 0.f;
    }
    __syncthreads();

    for (int o = tid; o < 640; o += 256) {
        int c = o & 15, kp = o >> 4;
        const float4* wr = (const float4*)(cw1s + c * 388);
        const float4* fr = (const float4*)(feat + kp * 388);
        unsigned long long s0 = 0ull, s1 = 0ull;
#pragma unroll 4
        for (int d = 0; d < 97; d++) {
            float4 w4 = wr[d], f4 = fr[d];
            ffma2(s0, pkf2(w4.x, w4.y), pkf2(f4.x, f4.y));
            ffma2(s1, pkf2(w4.z, w4.w), pkf2(f4.z, f4.w));
        }
        float a = cb1[c] + hsum2(s0) + hsum2(s1);
        y1[c * 40 + kp] = fmaxf(a, 0.f);
    }
    __syncthreads();

    for (int t = tid; t < 320; t += 256) {
        int c = t / 20, p = t % 20;
        mmp[t] = fmaxf(y1[c * 40 + 2 * p], y1[c * 40 + 2 * p + 1]);
    }
    __syncthreads();

    for (int t = tid; t < 512; t += 256) {
        int o2 = t >> 4, p = t & 15;
        float a = cb2[o2];
#pragma unroll
        for (int c = 0; c < 16; c++)
#pragma unroll
            for (int u = 0; u < 5; u++)
                a += cw2s[(o2 * 16 + c) * 5 + u] * mmp[c * 20 + p + u];
        g_flat[(size_t)g * 512 + t] = fmaxf(a, 0.f);
    }
}

// ---------------- final part 3: out = rr @ mW2 + mb2 ------------------------
__global__ void __launch_bounds__(256) out_k(
    const float* __restrict__ mW2, const float* __restrict__ mb2,
    float* __restrict__ out, int g0, int gcount)
{
    const int warp = threadIdx.x >> 5, lane = threadIdx.x & 31;
    const int gl = blockIdx.x * 8 + warp;
    if (gl >= gcount) return;
    const int g = g0 + gl;
    float s = 0.f;
#pragma unroll
    for (int q = 0; q < 4; q++) {
        int i = lane + 32 * q;
        s += g_P[(size_t)g * 128 + i] * mW2[i];
    }
    for (int off2 = 16; off2 > 0; off2 >>= 1)
        s += __shfl_down_sync(0xffffffffu, s, off2);
    if (lane == 0) out[g] = s + mb2[0];
}

// ---------------- host ------------------------------------------------------
extern "C" void kernel_launch(void* const* d_in, const int* in_sizes, int n_in,
                              void* d_out, int out_size)
{
    const float* x    = (const float*)d_in[0];
    const int*   z    = (const int*)  d_in[1];
    const int*   ei   = (const int*)  d_in[2];
    const float* ztab = (const float*)d_in[4];
    const float* W0   = (const float*)d_in[5];
    const float* b0   = (const float*)d_in[6];
    const float* W1   = (const float*)d_in[7];
    const float* b1   = (const float*)d_in[8];
    const float* W2   = (const float*)d_in[9];
    const float* b2   = (const float*)d_in[10];
    const float* W3   = (const float*)d_in[11];
    const float* b3   = (const float*)d_in[12];
    const float* cw1  = (const float*)d_in[13];
    const float* cb1  = (const float*)d_in[14];
    const float* cw2  = (const float*)d_in[15];
    const float* cb2  = (const float*)d_in[16];
    const float* mW1  = (const float*)d_in[17];
    const float* mb1  = (const float*)d_in[18];
    const float* mW2  = (const float*)d_in[19];
    const float* mb2  = (const float*)d_in[20];
    float* out = (float*)d_out;

    float *X0, *X1, *X2, *ZW, *Wh, *Wl, *flat, *P;
    cudaGetSymbolAddress((void**)&X0,  g_X0);
    cudaGetSymbolAddress((void**)&X1,  g_X1);
    cudaGetSymbolAddress((void**)&X2,  g_X2);
    cudaGetSymbolAddress((void**)&ZW,  g_ZW);
    cudaGetSymbolAddress((void**)&Wh,  g_Wh);
    cudaGetSymbolAddress((void**)&Wl,  g_Wl);
    cudaGetSymbolAddress((void**)&flat, g_flat);
    cudaGetSymbolAddress((void**)&P,   g_P);

    static cudaStream_t s1 = nullptr, s2 = nullptr;
    static cudaEvent_t  eR = nullptr, e1 = nullptr, e2 = nullptr;
    static bool init_done = false;
    if (!init_done) {
        cudaStreamCreateWithFlags(&s1, cudaStreamNonBlocking);
        cudaStreamCreateWithFlags(&s2, cudaStreamNonBlocking);
        cudaEventCreateWithFlags(&eR, cudaEventDisableTiming);
        cudaEventCreateWithFlags(&e1, cudaEventDisableTiming);
        cudaEventCreateWithFlags(&e2, cudaEventDisableTiming);
        cudaFuncSetAttribute((const void*)fused_layer<0>, cudaFuncAttributeMaxDynamicSharedMemorySize, FUSED_SMEM);
        cudaFuncSetAttribute((const void*)fused_layer<1>, cudaFuncAttributeMaxDynamicSharedMemorySize, FUSED_SMEM);
        cudaFuncSetAttribute((const void*)gemm_tc<128, 0>, cudaFuncAttributeMaxDynamicSharedMemorySize, GEMM_SM);
        cudaFuncSetAttribute((const void*)gemm_tc<512, 1>, cudaFuncAttributeMaxDynamicSharedMemorySize, GEMM_SM);
        cudaFuncSetAttribute((const void*)final_feat, cudaFuncAttributeMaxDynamicSharedMemorySize, FEAT_SMEM_FLOATS * 4);
        init_done = true;
    }

    const int MLP_GRID_H = (HALF + 127) / 128;   // 4

    // root: weight splits + ZW = ztab @ W0_top
    prep_gcn<<<256, 256>>>(W0, W1, W2);
    prep_mlp<<<256, 256>>>(mW1);
    gemm_tc<128, 0><<<8, 256, GEMM_SM>>>(ztab, Wh, Wl, nullptr, ZW, 1000);
    cudaEventRecord(eR, 0);
    cudaStreamWaitEvent(s1, eR, 0);
    cudaStreamWaitEvent(s2, eR, 0);

    for (int h = 0; h < 2; h++) {
        cudaStream_t s = h ? s2 : s1;
        const int g0 = h * HALF;
        const size_t rb = (size_t)g0 * NODES;

        build_csr<<<HALF, 256, 0, s>>>(ei, g0);

        fused_layer<1><<<HALF, 256, FUSED_SMEM, s>>>(
            x, z, ZW, Wh + 128 * 128, Wl + 128 * 128, b0, X0, g0);
        fused_layer<0><<<HALF, 256, FUSED_SMEM, s>>>(
            X0, nullptr, nullptr, Wh + 256 * 128, Wl + 256 * 128, b1, X1, g0);
        fused_layer<0><<<HALF, 256, FUSED_SMEM, s>>>(
            X1, nullptr, nullptr, Wh + 384 * 128, Wl + 384 * 128, b2, X2, g0);

        final_feat<<<HALF, 256, FEAT_SMEM_FLOATS * 4, s>>>(
            W3, b3, cw1, cb1, cw2, cb2, g0);

        gemm_tc<512, 1><<<MLP_GRID_H, 256, GEMM_SM, s>>>(
            flat + (size_t)g0 * 512, Wh + 512 * 128, Wl + 512 * 128,
            mb1, P + (size_t)g0 * 128, HALF);

        out_k<<<(HALF + 7) / 8, 256, 0, s>>>(mW2, mb2, out, g0, HALF);
    }

    cudaEventRecord(e1, s1);
    cudaEventRecord(e2, s2);
    cudaStreamWaitEvent(0, e1, 0);
    cudaStreamWaitEvent(0, e2, 0);
}

// round 15
// speedup vs baseline: 1.0057x; 1.0057x over previous
#include <cuda_runtime.h>
#include <cstdint>

#define NG    1000
#define NODES 100
#define EDGES 1600
#define NTOT  100000
#define ETOT  1600000
#define HID   128
#define KTOP  40
#define HALF  500
#define MH    (HALF * NODES)

// ---------------- scratch (device globals; no runtime allocation) ----------
__device__ float g_X0 [(size_t)NTOT * HID];
__device__ float g_X1 [(size_t)NTOT * HID];
__device__ float g_X2 [(size_t)NTOT * HID];
__device__ float g_ZW [1000 * HID];
__device__ float g_Wh [1024 * 128];
__device__ float g_Wl [1024 * 128];
__device__ float g_flat[(size_t)NG * 512];
__device__ float g_P  [(size_t)NG * 128];
__device__ int   g_off [NG * 101];
__device__ int2  g_edge[ETOT];

// ---------------- helpers ---------------------------------------------------
__device__ __forceinline__ float acc_tanh(float x) {
    float xc = fminf(fmaxf(x, -10.f), 10.f);
    float e  = __expf(2.f * xc);
    return (e - 1.f) / (e + 1.f);
}
__device__ __forceinline__ float f2tf32f(float x) {
    uint32_t r;
    asm("cvt.rna.tf32.f32 %0, %1;" : "=r"(r) : "f"(x));
    return __uint_as_float(r);
}
__device__ __forceinline__ void mma_tf32(float c[4], const uint32_t a[4],
                                         const uint32_t b0, const uint32_t b1) {
    asm volatile(
        "mma.sync.aligned.m16n8k8.row.col.f32.tf32.tf32.f32 "
        "{%0,%1,%2,%3}, {%4,%5,%6,%7}, {%8,%9}, {%0,%1,%2,%3};\n"
        : "+f"(c[0]), "+f"(c[1]), "+f"(c[2]), "+f"(c[3])
        : "r"(a[0]), "r"(a[1]), "r"(a[2]), "r"(a[3]), "r"(b0), "r"(b1));
}
__device__ __forceinline__ uint32_t smem_u32(const void* p) {
    return (uint32_t)__cvta_generic_to_shared(p);
}
#define CP16(dst, src) \
    asm volatile("cp.async.cg.shared.global [%0], [%1], 16;\n" :: "r"(dst), "l"(src))
#define CPCOMMIT() asm volatile("cp.async.commit_group;\n" ::: "memory")
#define CPWAIT2()  asm volatile("cp.async.wait_group 2;\n" ::: "memory")
#define CPWAIT1()  asm volatile("cp.async.wait_group 1;\n" ::: "memory")

__device__ __forceinline__ unsigned long long pkf2(float a, float b) {
    unsigned long long r;
    asm("mov.b64 %0, {%1, %2};" : "=l"(r) : "r"(__float_as_int(a)), "r"(__float_as_int(b)));
    return r;
}
__device__ __forceinline__ void ffma2(unsigned long long& d,
                                      unsigned long long a, unsigned long long b) {
    asm("fma.rn.f32x2 %0, %1, %2, %3;" : "=l"(d) : "l"(a), "l"(b), "l"(d));
}
__device__ __forceinline__ float hsum2(unsigned long long u) {
    int lo, hi;
    asm("mov.b64 {%0, %1}, %2;" : "=r"(lo), "=r"(hi) : "l"(u));
    return __int_as_float(lo) + __int_as_float(hi);
}

// ---------------- prep: pre-split weights into hi/lo ------------------------
// rows [0,128)=W0_top, [128,256)=W0_bot, [256,384)=W1, [384,512)=W2, [512,1024)=mW1
__global__ void __launch_bounds__(256) prep_gcn(
    const float* __restrict__ W0, const float* __restrict__ W1,
    const float* __restrict__ W2)
{
    int t = blockIdx.x * 256 + threadIdx.x;
    if (t >= 512 * 128) return;
    int row = t >> 7, col = t & 127;
    float v;
    if (row < 256)      v = W0[row * 128 + col];
    else if (row < 384) v = W1[(row - 256) * 128 + col];
    else                v = W2[(row - 384) * 128 + col];
    float h = f2tf32f(v);
    g_Wh[t] = h;
    g_Wl[t] = v - h;
}
__global__ void __launch_bounds__(256) prep_mlp(const float* __restrict__ mW1)
{
    int t = blockIdx.x * 256 + threadIdx.x;
    if (t >= 512 * 128) return;
    float v = mW1[t];
    float h = f2tf32f(v);
    g_Wh[512 * 128 + t] = h;
    g_Wl[512 * 128 + t] = v - h;
}

// ---------------- one-pass deterministic CSR --------------------------------
__global__ void __launch_bounds__(256) build_csr(const int* __restrict__ ei, int g0)
{
    __shared__ int2  sedge[EDGES];
    __shared__ int   hist [8][104];
    __shared__ int   cbase[8][104];
    __shared__ int   deg  [NODES];
    __shared__ float dinv [NODES];
    __shared__ int   offs [NODES + 1];

    const int g = g0 + blockIdx.x, tid = threadIdx.x;
    const int lane = tid & 31, warp = tid >> 5;
    const int base = g * NODES;
    const int* srce = ei + (size_t)g * EDGES;
    const int* dste = ei + (size_t)ETOT + (size_t)g * EDGES;

    for (int t = tid; t < 8 * 104; t += 256) ((int*)hist)[t] = 0;
    for (int e = tid; e < EDGES; e += 256)
        sedge[e] = make_int2(srce[e] - base, dste[e] - base);
    __syncthreads();

    const int cbeg = warp * 200;
    for (int j = lane; j < 200; j += 32)
        atomicAdd(&hist[warp][sedge[cbeg + j].y], 1);
    __syncthreads();

    if (tid < NODES) {
        int s = 0;
#pragma unroll
        for (int w = 0; w < 8; w++) s += hist[w][tid];
        deg[tid] = s;
        dinv[tid] = s > 0 ? rsqrtf((float)s) : 0.f;
    }
    __syncthreads();
    if (tid == 0) {
        int acc = 0;
        for (int i = 0; i < NODES; i++) { offs[i] = acc; acc += deg[i]; }
        offs[NODES] = acc;
    }
    __syncthreads();
    if (tid < NODES) {
        int run = offs[tid];
#pragma unroll
        for (int w = 0; w < 8; w++) {
            cbase[w][tid] = run;
            run += hist[w][tid];
            hist[w][tid] = 0;
        }
    }
    if (tid <= NODES) g_off[g * 101 + tid] = offs[tid];
    __syncthreads();

    const size_t gb = (size_t)g * EDGES;
    for (int j0 = 0; j0 < 200; j0 += 32) {
        int j = j0 + lane;
        bool act = j < 200;
        unsigned amask = __ballot_sync(0xffffffffu, act);
        if (act) {
            int2 sd = sedge[cbeg + j];
            unsigned mm = __match_any_sync(amask, sd.y);
            unsigned below = mm & ((1u << lane) - 1);
            int c = hist[warp][sd.y];
            __syncwarp(amask);
            g_edge[gb + cbase[warp][sd.y] + c + __popc(below)] =
                make_int2(sd.x, __float_as_int(dinv[sd.x] * dinv[sd.y]));
            if (below == 0)
                hist[warp][sd.y] = c + __popc(mm);
        }
        __syncwarp();
    }
}

// ---------------- fused layer: GEMM (3xTF32) + agg + tanh, 1 CTA per graph --
// T kept in SMEM; edges prefetched via cp.async group 0.
#define FL_ASL 1024          // 128 rows * 8 (rows >=100 unwritten, discarded)
#define FL_BSL 2112          // Bh 8*132 + Bl 8*132
#define FUSED_SMEM ((3 * FL_ASL + 3 * FL_BSL + 100 * 132 + EDGES * 2 + 104) * 4)

template <int ZADD>
__global__ void __launch_bounds__(256, 2) fused_layer(
    const float* __restrict__ Aa, const int* __restrict__ z,
    const float* __restrict__ ZW,
    const float* __restrict__ Wh, const float* __restrict__ Wl,
    const float* __restrict__ bias, float* __restrict__ Xout, int g0)
{
    extern __shared__ float sm[];
    float* As   = sm;                       // 3*1024
    float* Bs   = As + 3 * FL_ASL;          // 3*2112
    float* Ts   = Bs + 3 * FL_BSL;          // 100*132
    int2*  sed  = (int2*)(Ts + 100 * 132);  // 1600
    int*   soff = (int*)(sed + EDGES);      // 104

    const int g = g0 + blockIdx.x, tid = threadIdx.x;
    const int lane = tid & 31, wid = tid >> 5;
    const int wm = wid & 1, wn = wid >> 1;
    const int l4 = lane >> 2, lm = lane & 3;

    const int arow = tid >> 1, ahalf = (tid & 1) * 4;   // valid for tid<200
    const int bk = tid >> 5, bn4 = (tid & 31) * 4;

    const float* aptr  = Aa + ((size_t)g * NODES + arow) * HID;
    const float* bptrH = Wh + (size_t)bk * HID + bn4;
    const float* bptrL = Wl + (size_t)bk * HID + bn4;
    const uint32_t adst = smem_u32(As + arow * 8 + ahalf);
    const uint32_t bdst = smem_u32(Bs + bk * 132 + bn4);

    // --- group 0: prefetch edge list (hidden under mma pipeline) ------------
    {
        const int4* egi = (const int4*)(g_edge + (size_t)g * EDGES);
        const uint32_t sdst = smem_u32(sed);
        for (int t = tid; t < EDGES / 2; t += 256)
            CP16(sdst + t * 16, egi + t);
        CPCOMMIT();
    }

    auto issue = [&](int s) {
        const int buf = s % 3;
        if (tid < 200)
            CP16(adst + buf * (FL_ASL * 4), aptr + s * 8 + ahalf);
        CP16(bdst + buf * (FL_BSL * 4), bptrH + (size_t)s * 8 * HID);
        CP16(bdst + buf * (FL_BSL * 4) + 4224, bptrL + (size_t)s * 8 * HID);
        CPCOMMIT();
    };

    float acc[4][4][4];
#pragma unroll
    for (int mi = 0; mi < 4; mi++)
#pragma unroll
        for (int nj = 0; nj < 4; nj++)
#pragma unroll
            for (int q = 0; q < 4; q++) acc[mi][nj][q] = 0.f;

    issue(0); issue(1);

    // offsets (regular loads; latency hidden behind pipeline)
    if (tid <= NODES) soff[tid] = g_off[g * 101 + tid];

#pragma unroll 1
    for (int s = 0; s < 16; s++) {
        CPWAIT1();
        __syncthreads();
        if (s + 2 < 16) issue(s + 2);

        const float* A0  = As + (s % 3) * FL_ASL;
        const float* B0h = Bs + (s % 3) * FL_BSL;
        const float* B0l = B0h + 1056;

        uint32_t bh[4][2], bl[4][2];
#pragma unroll
        for (int nj = 0; nj < 4; nj++) {
            int n = wn * 32 + nj * 8 + l4;
            bh[nj][0] = __float_as_uint(B0h[lm * 132 + n]);
            bh[nj][1] = __float_as_uint(B0h[(lm + 4) * 132 + n]);
            bl[nj][0] = __float_as_uint(B0l[lm * 132 + n]);
            bl[nj][1] = __float_as_uint(B0l[(lm + 4) * 132 + n]);
        }
#pragma unroll
        for (int mi = 0; mi < 4; mi++) {
            int r = (wm * 4 + mi) * 16 + l4;
            float r0 = A0[r * 8 + lm];
            float r1 = A0[(r + 8) * 8 + lm];
            float r2 = A0[r * 8 + lm + 4];
            float r3 = A0[(r + 8) * 8 + lm + 4];
            float h0 = f2tf32f(r0), h1 = f2tf32f(r1);
            float h2 = f2tf32f(r2), h3 = f2tf32f(r3);
            uint32_t ah[4] = { __float_as_uint(h0), __float_as_uint(h1),
                               __float_as_uint(h2), __float_as_uint(h3) };
            uint32_t al[4] = { __float_as_uint(r0 - h0), __float_as_uint(r1 - h1),
                               __float_as_uint(r2 - h2), __float_as_uint(r3 - h3) };
#pragma unroll
            for (int nj = 0; nj < 4; nj++) {
                mma_tf32(acc[mi][nj], ah, bh[nj][0], bh[nj][1]);
                mma_tf32(acc[mi][nj], ah, bl[nj][0], bl[nj][1]);
                mma_tf32(acc[mi][nj], al, bh[nj][0], bh[nj][1]);
            }
        }
        __syncthreads();
    }

    // --- epilogue: T -> SMEM (stride 132), + ZW[z] for layer 0 ---------------
#pragma unroll
    for (int mi = 0; mi < 4; mi++) {
        int r = wm * 64 + mi * 16 + l4;
        const float* zw0 = nullptr;
        const float* zw1 = nullptr;
        if (ZADD) {
            zw0 = ZW + (size_t)((r     < NODES) ? z[(size_t)g * NODES + r]     : 0) * HID;
            zw1 = ZW + (size_t)((r + 8 < NODES) ? z[(size_t)g * NODES + r + 8] : 0) * HID;
        }
#pragma unroll
        for (int nj = 0; nj < 4; nj++) {
            int c = wn * 32 + nj * 8 + 2 * lm;
            float v0 = acc[mi][nj][0], v1 = acc[mi][nj][1];
            float v2 = acc[mi][nj][2], v3 = acc[mi][nj][3];
            if (ZADD) {
                v0 += zw0[c]; v1 += zw0[c + 1];
                v2 += zw1[c]; v3 += zw1[c + 1];
            }
            if (r < NODES)
                *(float2*)&Ts[r * 132 + c] = make_float2(v0, v1);
            if (r + 8 < NODES)
                *(float2*)&Ts[(r + 8) * 132 + c] = make_float2(v2, v3);
        }
    }
    asm volatile("cp.async.wait_group 0;\n" ::: "memory");  // edges ready
    __syncthreads();

    // --- aggregation + tanh from SMEM T --------------------------------------
    const float4 bv = *(const float4*)(bias + lane * 4);
    for (int d = wid; d < NODES; d += 8) {
        int e0 = soff[d], e1 = soff[d + 1];
        float4 a4 = make_float4(0.f, 0.f, 0.f, 0.f);
        if (e0 < e1) {
            int2 p0 = sed[e0];
            float4 t0 = *(const float4*)&Ts[p0.x * 132 + lane * 4];
#pragma unroll 2
            for (int e = e0 + 1; e < e1; e++) {
                int2 p1 = sed[e];
                float4 t1 = *(const float4*)&Ts[p1.x * 132 + lane * 4];
                float w = __int_as_float(p0.y);
                a4.x += w * t0.x; a4.y += w * t0.y;
                a4.z += w * t0.z; a4.w += w * t0.w;
                p0 = p1; t0 = t1;
            }
            float w = __int_as_float(p0.y);
            a4.x += w * t0.x; a4.y += w * t0.y;
            a4.z += w * t0.z; a4.w += w * t0.w;
        }
        float4 o;
        o.x = acc_tanh(a4.x + bv.x);
        o.y = acc_tanh(a4.y + bv.y);
        o.z = acc_tanh(a4.z + bv.z);
        o.w = acc_tanh(a4.w + bv.w);
        *(float4*)(Xout + ((size_t)g * NODES + d) * HID + lane * 4) = o;
    }
}

// ---------------- generic tensor-core GEMM (ZW prep + mlp1) ------------------
#define B_SLICE 2112
#define A_SLICE 1024
#define GEMM_SM ((4 * A_SLICE + 4 * B_SLICE) * 4)

template <int K, int RELU>
__global__ void __launch_bounds__(256, 2) gemm_tc(
    const float* __restrict__ Aa,
    const float* __restrict__ Wh, const float* __restrict__ Wl,
    const float* __restrict__ bias, float* __restrict__ C, int M)
{
    extern __shared__ float sm[];
    float* As = sm;
    float* Bs = sm + 4 * A_SLICE;

    const int tid = threadIdx.x;
    const int lane = tid & 31, wid = tid >> 5;
    const int wm = wid & 1, wn = wid >> 1;
    const int l4 = lane >> 2, lm = lane & 3;
    const int row0 = blockIdx.x * 128;

    const int arow = tid >> 1, ahalf = (tid & 1) * 4;
    const int bk = tid >> 5, bn4 = (tid & 31) * 4;

    const int gr = row0 + arow;
    const int grc = gr < M ? gr : (M - 1);
    const float* aptr = Aa + (size_t)grc * K;
    const float* bptrH = Wh + (size_t)bk * HID + bn4;
    const float* bptrL = Wl + (size_t)bk * HID + bn4;
    const uint32_t adst = smem_u32(As + arow * 8 + ahalf);
    const uint32_t bdst = smem_u32(Bs + bk * 132 + bn4);

    const int S = K / 8;

    auto issue = [&](int s) {
        const int buf = s & 3;
        CP16(adst + buf * (A_SLICE * 4), aptr + s * 8 + ahalf);
        CP16(bdst + buf * (B_SLICE * 4), bptrH + (size_t)s * 8 * HID);
        CP16(bdst + buf * (B_SLICE * 4) + 4224, bptrL + (size_t)s * 8 * HID);
        CPCOMMIT();
    };

    float acc[4][4][4];
#pragma unroll
    for (int mi = 0; mi < 4; mi++)
#pragma unroll
        for (int nj = 0; nj < 4; nj++)
#pragma unroll
            for (int q = 0; q < 4; q++) acc[mi][nj][q] = 0.f;

    issue(0); issue(1); issue(2);

#pragma unroll 1
    for (int s = 0; s < S; s++) {
        CPWAIT2();
        __syncthreads();
        if (s + 3 < S) issue(s + 3);

        const float* A0  = As + (s & 3) * A_SLICE;
        const float* B0h = Bs + (s & 3) * B_SLICE;
        const float* B0l = B0h + 1056;

        uint32_t bh[4][2], bl[4][2];
#pragma unroll
        for (int nj = 0; nj < 4; nj++) {
            int n = wn * 32 + nj * 8 + l4;
            bh[nj][0] = __float_as_uint(B0h[lm * 132 + n]);
            bh[nj][1] = __float_as_uint(B0h[(lm + 4) * 132 + n]);
            bl[nj][0] = __float_as_uint(B0l[lm * 132 + n]);
            bl[nj][1] = __float_as_uint(B0l[(lm + 4) * 132 + n]);
        }
#pragma unroll
        for (int mi = 0; mi < 4; mi++) {
            int r = (wm * 4 + mi) * 16 + l4;
            float r0 = A0[r * 8 + lm];
            float r1 = A0[(r + 8) * 8 + lm];
            float r2 = A0[r * 8 + lm + 4];
            float r3 = A0[(r + 8) * 8 + lm + 4];
            float h0 = f2tf32f(r0), h1 = f2tf32f(r1);
            float h2 = f2tf32f(r2), h3 = f2tf32f(r3);
            uint32_t ah[4] = { __float_as_uint(h0), __float_as_uint(h1),
                               __float_as_uint(h2), __float_as_uint(h3) };
            uint32_t al[4] = { __float_as_uint(r0 - h0), __float_as_uint(r1 - h1),
                               __float_as_uint(r2 - h2), __float_as_uint(r3 - h3) };
#pragma unroll
            for (int nj = 0; nj < 4; nj++) {
                mma_tf32(acc[mi][nj], ah, bh[nj][0], bh[nj][1]);
                mma_tf32(acc[mi][nj], ah, bl[nj][0], bl[nj][1]);
                mma_tf32(acc[mi][nj], al, bh[nj][0], bh[nj][1]);
            }
        }
        __syncthreads();
    }

#pragma unroll
    for (int mi = 0; mi < 4; mi++) {
#pragma unroll
        for (int nj = 0; nj < 4; nj++) {
            int r = row0 + wm * 64 + mi * 16 + l4;
            int c = wn * 32 + nj * 8 + 2 * lm;
            float v0 = acc[mi][nj][0], v1 = acc[mi][nj][1];
            float v2 = acc[mi][nj][2], v3 = acc[mi][nj][3];
            if (RELU) {
                float b0v = bias[c], b1v = bias[c + 1];
                v0 = fmaxf(v0 + b0v, 0.f); v1 = fmaxf(v1 + b1v, 0.f);
                v2 = fmaxf(v2 + b0v, 0.f); v3 = fmaxf(v3 + b1v, 0.f);
            }
            if (r < M)
                *(float2*)(C + (size_t)r * HID + c) = make_float2(v0, v1);
            if (r + 8 < M)
                *(float2*)(C + (size_t)(r + 8) * HID + c) = make_float2(v2, v3);
        }
    }
}

// ---------------- final part 1: layer3 + sort-pool + conv1/2 -> flat --------
#define FEAT_SMEM_FLOATS 25616
__global__ void __launch_bounds__(256) final_feat(
    const float* __restrict__ W3,  const float* __restrict__ b3,
    const float* __restrict__ cw1, const float* __restrict__ cb1,
    const float* __restrict__ cw2, const float* __restrict__ cb2, int g0)
{
    extern __shared__ float sm[];
    float* W3s  = sm;
    float* cw1s = W3s + 128;
    float* cw2s = cw1s + 6208;
    float* feat = cw2s + 2560;
    float* t3   = feat + 15520;
    float* x3   = t3 + 100;
    float* y1   = x3 + 100;
    float* mmp  = y1 + 640;
    int*   topi = (int*)(mmp + 320);

    const int g = g0 + blockIdx.x, tid = threadIdx.x;
    const float* X2g = g_X2 + (size_t)g * NODES * HID;

    if (tid < 128) W3s[tid] = W3[tid];
    for (int t = tid; t < 16 * 385; t += 256) {
        int c = t / 385, d = t - c * 385;
        cw1s[c * 388 + d] = cw1[t];
    }
    if (tid < 16) {
        cw1s[tid * 388 + 385] = 0.f;
        cw1s[tid * 388 + 386] = 0.f;
        cw1s[tid * 388 + 387] = 0.f;
    }
    for (int t = tid; t < 2560; t += 256) cw2s[t] = cw2[t];
    __syncthreads();

    if (tid < NODES) {
        const float4* xr = (const float4*)(X2g + (size_t)tid * HID);
        const float4* wr = (const float4*)W3s;
        float a = 0.f;
#pragma unroll 8
        for (int k = 0; k < 32; k++) {
            float4 xv = xr[k], wv = wr[k];
            a += xv.x * wv.x + xv.y * wv.y + xv.z * wv.z + xv.w * wv.w;
        }
        t3[tid] = a;
    }
    __syncthreads();

    if (tid < NODES) {
        const int*  offp = g_off + g * 101;
        const int2* ep   = g_edge + (size_t)g * EDGES;
        float a = 0.f;
        int e1 = offp[tid + 1];
        for (int e = offp[tid]; e < e1; e++) {
            int2 pe = ep[e];
            a += __int_as_float(pe.y) * t3[pe.x];
        }
        x3[tid] = acc_tanh(a + b3[0]);
    }
    __syncthreads();

    if (tid < NODES) {
        float v = x3[tid];
        int r = 0;
        for (int j = 0; j < NODES; j++) {
            float u = x3[j];
            r += (u > v) || (u == v && j < tid);
        }
        if (r < KTOP) topi[r] = tid;
    }
    __syncthreads();

    for (int t = tid; t < KTOP * HID; t += 256) {
        int k = t >> 7, d = t & 127;
        int node = topi[k];
        size_t gbase = ((size_t)g * NODES + node) * HID + d;
        feat[k * 388 + d]       = g_X0[gbase];
        feat[k * 388 + 128 + d] = g_X1[gbase];
        feat[k * 388 + 256 + d] = g_X2[gbase];
    }
    if (tid < KTOP) {
        feat[tid * 388 + 384] = x3[topi[tid]];
        feat[tid * 388 + 385] = 0.f;
        feat[tid * 388 + 386] = 0.f;
        feat[tid * 388 + 387] = 0.f;
    }
    __syncthreads();

    for (int o = tid; o < 640; o += 256) {
        int c = o & 15, kp = o >> 4;
        const float4* wr = (const float4*)(cw1s + c * 388);
        const float4* fr = (const float4*)(feat + kp * 388);
        unsigned long long s0 = 0ull, s1 = 0ull;
#pragma unroll 4
        for (int d = 0; d < 97; d++) {
            float4 w4 = wr[d], f4 = fr[d];
            ffma2(s0, pkf2(w4.x, w4.y), pkf2(f4.x, f4.y));
            ffma2(s1, pkf2(w4.z, w4.w), pkf2(f4.z, f4.w));
        }
        float a = cb1[c] + hsum2(s0) + hsum2(s1);
        y1[c * 40 + kp] = fmaxf(a, 0.f);
    }
    __syncthreads();

    for (int t = tid; t < 320; t += 256) {
        int c = t / 20, p = t % 20;
        mmp[t] = fmaxf(y1[c * 40 + 2 * p], y1[c * 40 + 2 * p + 1]);
    }
    __syncthreads();

    for (int t = tid; t < 512; t += 256) {
        int o2 = t >> 4, p = t & 15;
        float a = cb2[o2];
#pragma unroll
        for (int c = 0; c < 16; c++)
#pragma unroll
            for (int u = 0; u < 5; u++)
                a += cw2s[(o2 * 16 + c) * 5 + u] * mmp[c * 20 + p + u];
        g_flat[(size_t)g * 512 + t] = fmaxf(a, 0.f);
    }
}

// ---------------- final part 3: out = rr @ mW2 + mb2 ------------------------
__global__ void __launch_bounds__(256) out_k(
    const float* __restrict__ mW2, const float* __restrict__ mb2,
    float* __restrict__ out, int g0, int gcount)
{
    const int warp = threadIdx.x >> 5, lane = threadIdx.x & 31;
    const int gl = blockIdx.x * 8 + warp;
    if (gl >= gcount) return;
    const int g = g0 + gl;
    float s = 0.f;
#pragma unroll
    for (int q = 0; q < 4; q++) {
        int i = lane + 32 * q;
        s += g_P[(size_t)g * 128 + i] * mW2[i];
    }
    for (int off2 = 16; off2 > 0; off2 >>= 1)
        s += __shfl_down_sync(0xffffffffu, s, off2);
    if (lane == 0) out[g] = s + mb2[0];
}

// ---------------- host ------------------------------------------------------
extern "C" void kernel_launch(void* const* d_in, const int* in_sizes, int n_in,
                              void* d_out, int out_size)
{
    const float* x    = (const float*)d_in[0];
    const int*   z    = (const int*)  d_in[1];
    const int*   ei   = (const int*)  d_in[2];
    const float* ztab = (const float*)d_in[4];
    const float* W0   = (const float*)d_in[5];
    const float* b0   = (const float*)d_in[6];
    const float* W1   = (const float*)d_in[7];
    const float* b1   = (const float*)d_in[8];
    const float* W2   = (const float*)d_in[9];
    const float* b2   = (const float*)d_in[10];
    const float* W3   = (const float*)d_in[11];
    const float* b3   = (const float*)d_in[12];
    const float* cw1  = (const float*)d_in[13];
    const float* cb1  = (const float*)d_in[14];
    const float* cw2  = (const float*)d_in[15];
    const float* cb2  = (const float*)d_in[16];
    const float* mW1  = (const float*)d_in[17];
    const float* mb1  = (const float*)d_in[18];
    const float* mW2  = (const float*)d_in[19];
    const float* mb2  = (const float*)d_in[20];
    float* out = (float*)d_out;

    float *X0, *X1, *X2, *ZW, *Wh, *Wl, *flat, *P;
    cudaGetSymbolAddress((void**)&X0,  g_X0);
    cudaGetSymbolAddress((void**)&X1,  g_X1);
    cudaGetSymbolAddress((void**)&X2,  g_X2);
    cudaGetSymbolAddress((void**)&ZW,  g_ZW);
    cudaGetSymbolAddress((void**)&Wh,  g_Wh);
    cudaGetSymbolAddress((void**)&Wl,  g_Wl);
    cudaGetSymbolAddress((void**)&flat, g_flat);
    cudaGetSymbolAddress((void**)&P,   g_P);

    static cudaStream_t s1 = nullptr, s2 = nullptr;
    static cudaEvent_t  eR = nullptr, e1 = nullptr, e2 = nullptr;
    static bool init_done = false;
    if (!init_done) {
        cudaStreamCreateWithFlags(&s1, cudaStreamNonBlocking);
        cudaStreamCreateWithFlags(&s2, cudaStreamNonBlocking);
        cudaEventCreateWithFlags(&eR, cudaEventDisableTiming);
        cudaEventCreateWithFlags(&e1, cudaEventDisableTiming);
        cudaEventCreateWithFlags(&e2, cudaEventDisableTiming);
        cudaFuncSetAttribute((const void*)fused_layer<0>, cudaFuncAttributeMaxDynamicSharedMemorySize, FUSED_SMEM);
        cudaFuncSetAttribute((const void*)fused_layer<1>, cudaFuncAttributeMaxDynamicSharedMemorySize, FUSED_SMEM);
        cudaFuncSetAttribute((const void*)gemm_tc<128, 0>, cudaFuncAttributeMaxDynamicSharedMemorySize, GEMM_SM);
        cudaFuncSetAttribute((const void*)gemm_tc<512, 1>, cudaFuncAttributeMaxDynamicSharedMemorySize, GEMM_SM);
        cudaFuncSetAttribute((const void*)final_feat, cudaFuncAttributeMaxDynamicSharedMemorySize, FEAT_SMEM_FLOATS * 4);
        init_done = true;
    }

    const int MLP_GRID_H = (HALF + 127) / 128;   // 4

    // root: weight splits + ZW = ztab @ W0_top
    prep_gcn<<<256, 256>>>(W0, W1, W2);
    prep_mlp<<<256, 256>>>(mW1);
    gemm_tc<128, 0><<<8, 256, GEMM_SM>>>(ztab, Wh, Wl, nullptr, ZW, 1000);
    cudaEventRecord(eR, 0);
    cudaStreamWaitEvent(s1, eR, 0);
    cudaStreamWaitEvent(s2, eR, 0);

    for (int h = 0; h < 2; h++) {
        cudaStream_t s = h ? s2 : s1;
        const int g0 = h * HALF;
        const size_t rb = (size_t)g0 * NODES;

        build_csr<<<HALF, 256, 0, s>>>(ei, g0);

        fused_layer<1><<<HALF, 256, FUSED_SMEM, s>>>(
            x, z, ZW, Wh + 128 * 128, Wl + 128 * 128, b0, X0, g0);
        fused_layer<0><<<HALF, 256, FUSED_SMEM, s>>>(
            X0, nullptr, nullptr, Wh + 256 * 128, Wl + 256 * 128, b1, X1, g0);
        fused_layer<0><<<HALF, 256, FUSED_SMEM, s>>>(
            X1, nullptr, nullptr, Wh + 384 * 128, Wl + 384 * 128, b2, X2, g0);

        final_feat<<<HALF, 256, FEAT_SMEM_FLOATS * 4, s>>>(
            W3, b3, cw1, cb1, cw2, cb2, g0);

        gemm_tc<512, 1><<<MLP_GRID_H, 256, GEMM_SM, s>>>(
            flat + (size_t)g0 * 512, Wh + 512 * 128, Wl + 512 * 128,
            mb1, P + (size_t)g0 * 128, HALF);

        out_k<<<(HALF + 7) / 8, 256, 0, s>>>(mW2, mb2, out, g0, HALF);
    }

    cudaEventRecord(e1, s1);
    cudaEventRecord(e2, s2);
    cudaStreamWaitEvent(0, e1, 0);
    cudaStreamWaitEvent(0, e2, 0);
}

// round 16
// speedup vs baseline: 1.0754x; 1.0694x over previous
#include <cuda_runtime.h>
#include <cstdint>

#define NG    1000
#define NODES 100
#define EDGES 1600
#define NTOT  100000
#define ETOT  1600000
#define HID   128
#define KTOP  40
#define HALF  500
#define MH    (HALF * NODES)

// ---------------- scratch (device globals; no runtime allocation) ----------
__device__ float g_T  [(size_t)NTOT * HID];
__device__ float g_X0 [(size_t)NTOT * HID];
__device__ float g_X1 [(size_t)NTOT * HID];
__device__ float g_X2 [(size_t)NTOT * HID];
__device__ float g_ZW [1000 * HID];
__device__ float g_Wh [1024 * 128];
__device__ float g_Wl [1024 * 128];
__device__ float g_flat[(size_t)NG * 512];
__device__ float g_P  [(size_t)NG * 128];
__device__ int   g_off [NG * 101];
__device__ int2  g_edge[ETOT];

// ---------------- helpers ---------------------------------------------------
__device__ __forceinline__ float acc_tanh(float x) {
    float xc = fminf(fmaxf(x, -10.f), 10.f);
    float e  = __expf(2.f * xc);
    return (e - 1.f) / (e + 1.f);
}
__device__ __forceinline__ float f2tf32f(float x) {
    uint32_t r;
    asm("cvt.rna.tf32.f32 %0, %1;" : "=r"(r) : "f"(x));
    return __uint_as_float(r);
}
__device__ __forceinline__ void mma_tf32(float c[4], const uint32_t a[4],
                                         const uint32_t b0, const uint32_t b1) {
    asm volatile(
        "mma.sync.aligned.m16n8k8.row.col.f32.tf32.tf32.f32 "
        "{%0,%1,%2,%3}, {%4,%5,%6,%7}, {%8,%9}, {%0,%1,%2,%3};\n"
        : "+f"(c[0]), "+f"(c[1]), "+f"(c[2]), "+f"(c[3])
        : "r"(a[0]), "r"(a[1]), "r"(a[2]), "r"(a[3]), "r"(b0), "r"(b1));
}
__device__ __forceinline__ uint32_t smem_u32(const void* p) {
    return (uint32_t)__cvta_generic_to_shared(p);
}
#define CP16(dst, src) \
    asm volatile("cp.async.cg.shared.global [%0], [%1], 16;\n" :: "r"(dst), "l"(src))
#define CPCOMMIT() asm volatile("cp.async.commit_group;\n" ::: "memory")
#define CPWAIT2()  asm volatile("cp.async.wait_group 2;\n" ::: "memory")

__device__ __forceinline__ unsigned long long pkf2(float a, float b) {
    unsigned long long r;
    asm("mov.b64 %0, {%1, %2};" : "=l"(r) : "r"(__float_as_int(a)), "r"(__float_as_int(b)));
    return r;
}
__device__ __forceinline__ unsigned long long pk2i(int x) {
    unsigned long long r;
    asm("mov.b64 %0, {%1, %1};" : "=l"(r) : "r"(x));
    return r;
}
__device__ __forceinline__ void ffma2(unsigned long long& d,
                                      unsigned long long a, unsigned long long b) {
    asm("fma.rn.f32x2 %0, %1, %2, %3;" : "=l"(d) : "l"(a), "l"(b), "l"(d));
}
__device__ __forceinline__ float hsum2(unsigned long long u) {
    int lo, hi;
    asm("mov.b64 {%0, %1}, %2;" : "=r"(lo), "=r"(hi) : "l"(u));
    return __int_as_float(lo) + __int_as_float(hi);
}
__device__ __forceinline__ float2 up2(unsigned long long u) {
    int lo, hi;
    asm("mov.b64 {%0, %1}, %2;" : "=r"(lo), "=r"(hi) : "l"(u));
    return make_float2(__int_as_float(lo), __int_as_float(hi));
}

// ---------------- prep: pre-split weights into hi/lo ------------------------
// rows [0,128)=W0_top, [128,256)=W0_bot, [256,384)=W1, [384,512)=W2, [512,1024)=mW1
__global__ void __launch_bounds__(256) prep_gcn(
    const float* __restrict__ W0, const float* __restrict__ W1,
    const float* __restrict__ W2)
{
    int t = blockIdx.x * 256 + threadIdx.x;
    if (t >= 512 * 128) return;
    int row = t >> 7, col = t & 127;
    float v;
    if (row < 256)      v = W0[row * 128 + col];
    else if (row < 384) v = W1[(row - 256) * 128 + col];
    else                v = W2[(row - 384) * 128 + col];
    float h = f2tf32f(v);
    g_Wh[t] = h;
    g_Wl[t] = v - h;
}
__global__ void __launch_bounds__(256) prep_mlp(const float* __restrict__ mW1)
{
    int t = blockIdx.x * 256 + threadIdx.x;
    if (t >= 512 * 128) return;
    float v = mW1[t];
    float h = f2tf32f(v);
    g_Wh[512 * 128 + t] = h;
    g_Wl[512 * 128 + t] = v - h;
}

// ---------------- one-pass deterministic CSR --------------------------------
__global__ void __launch_bounds__(256) build_csr(const int* __restrict__ ei, int g0)
{
    __shared__ int2  sedge[EDGES];
    __shared__ int   hist [8][104];
    __shared__ int   cbase[8][104];
    __shared__ int   deg  [NODES];
    __shared__ float dinv [NODES];
    __shared__ int   offs [NODES + 1];

    const int g = g0 + blockIdx.x, tid = threadIdx.x;
    const int lane = tid & 31, warp = tid >> 5;
    const int base = g * NODES;
    const int* srce = ei + (size_t)g * EDGES;
    const int* dste = ei + (size_t)ETOT + (size_t)g * EDGES;

    for (int t = tid; t < 8 * 104; t += 256) ((int*)hist)[t] = 0;
    for (int e = tid; e < EDGES; e += 256)
        sedge[e] = make_int2(srce[e] - base, dste[e] - base);
    __syncthreads();

    const int cbeg = warp * 200;
    for (int j = lane; j < 200; j += 32)
        atomicAdd(&hist[warp][sedge[cbeg + j].y], 1);
    __syncthreads();

    if (tid < NODES) {
        int s = 0;
#pragma unroll
        for (int w = 0; w < 8; w++) s += hist[w][tid];
        deg[tid] = s;
        dinv[tid] = s > 0 ? rsqrtf((float)s) : 0.f;
    }
    __syncthreads();
    if (tid == 0) {
        int acc = 0;
        for (int i = 0; i < NODES; i++) { offs[i] = acc; acc += deg[i]; }
        offs[NODES] = acc;
    }
    __syncthreads();
    if (tid < NODES) {
        int run = offs[tid];
#pragma unroll
        for (int w = 0; w < 8; w++) {
            cbase[w][tid] = run;
            run += hist[w][tid];
            hist[w][tid] = 0;
        }
    }
    if (tid <= NODES) g_off[g * 101 + tid] = offs[tid];
    __syncthreads();

    const size_t gb = (size_t)g * EDGES;
    for (int j0 = 0; j0 < 200; j0 += 32) {
        int j = j0 + lane;
        bool act = j < 200;
        unsigned amask = __ballot_sync(0xffffffffu, act);
        if (act) {
            int2 sd = sedge[cbeg + j];
            unsigned mm = __match_any_sync(amask, sd.y);
            unsigned below = mm & ((1u << lane) - 1);
            int c = hist[warp][sd.y];
            __syncwarp(amask);
            g_edge[gb + cbase[warp][sd.y] + c + __popc(below)] =
                make_int2(sd.x, __float_as_int(dinv[sd.x] * dinv[sd.y]));
            if (below == 0)
                hist[warp][sd.y] = c + __popc(mm);
        }
        __syncwarp();
    }
}

// ---------------- tensor-core 3xTF32 GEMM -----------------------------------
// C[M,128] = A[M,K] @ W[K,128]; A raw fp32 (runtime hi/lo split), W pre-split.
// RELU: C = relu(acc + bias[col]).  ZADD: C += ZW[z[row]] (layer-0 z-table term).
#define B_SLICE 2112
#define A_SLICE 1024
#define GEMM_SM ((4 * A_SLICE + 4 * B_SLICE) * 4)   // 50176 B

template <int K, int RELU, int ZADD>
__global__ void __launch_bounds__(256, 2) gemm_tc(
    const float* __restrict__ Aa, const int* __restrict__ z,
    const float* __restrict__ ZW,
    const float* __restrict__ Wh, const float* __restrict__ Wl,
    const float* __restrict__ bias, float* __restrict__ C, int M)
{
    extern __shared__ float sm[];
    float* As = sm;
    float* Bs = sm + 4 * A_SLICE;

    const int tid = threadIdx.x;
    const int lane = tid & 31, wid = tid >> 5;
    const int wm = wid & 1, wn = wid >> 1;
    const int l4 = lane >> 2, lm = lane & 3;
    const int row0 = blockIdx.x * 128;

    const int arow = tid >> 1, ahalf = (tid & 1) * 4;
    const int bk = tid >> 5, bn4 = (tid & 31) * 4;

    const int gr = row0 + arow;
    const int grc = gr < M ? gr : (M - 1);
    const float* aptr = Aa + (size_t)grc * K;
    const float* bptrH = Wh + (size_t)bk * HID + bn4;
    const float* bptrL = Wl + (size_t)bk * HID + bn4;
    const uint32_t adst = smem_u32(As + arow * 8 + ahalf);
    const uint32_t bdst = smem_u32(Bs + bk * 132 + bn4);

    const int S = K / 8;

    auto issue = [&](int s) {
        const int buf = s & 3;
        CP16(adst + buf * (A_SLICE * 4), aptr + s * 8 + ahalf);
        CP16(bdst + buf * (B_SLICE * 4), bptrH + (size_t)s * 8 * HID);
        CP16(bdst + buf * (B_SLICE * 4) + 4224, bptrL + (size_t)s * 8 * HID);
        CPCOMMIT();
    };

    float acc[4][4][4];
#pragma unroll
    for (int mi = 0; mi < 4; mi++)
#pragma unroll
        for (int nj = 0; nj < 4; nj++)
#pragma unroll
            for (int q = 0; q < 4; q++) acc[mi][nj][q] = 0.f;

    issue(0); issue(1); issue(2);

#pragma unroll 1
    for (int s = 0; s < S; s++) {
        CPWAIT2();
        __syncthreads();
        if (s + 3 < S) issue(s + 3);

        const float* A0  = As + (s & 3) * A_SLICE;
        const float* B0h = Bs + (s & 3) * B_SLICE;
        const float* B0l = B0h + 1056;

        uint32_t bh[4][2], bl[4][2];
#pragma unroll
        for (int nj = 0; nj < 4; nj++) {
            int n = wn * 32 + nj * 8 + l4;
            bh[nj][0] = __float_as_uint(B0h[lm * 132 + n]);
            bh[nj][1] = __float_as_uint(B0h[(lm + 4) * 132 + n]);
            bl[nj][0] = __float_as_uint(B0l[lm * 132 + n]);
            bl[nj][1] = __float_as_uint(B0l[(lm + 4) * 132 + n]);
        }
#pragma unroll
        for (int mi = 0; mi < 4; mi++) {
            int r = (wm * 4 + mi) * 16 + l4;
            float r0 = A0[r * 8 + lm];
            float r1 = A0[(r + 8) * 8 + lm];
            float r2 = A0[r * 8 + lm + 4];
            float r3 = A0[(r + 8) * 8 + lm + 4];
            float h0 = f2tf32f(r0), h1 = f2tf32f(r1);
            float h2 = f2tf32f(r2), h3 = f2tf32f(r3);
            uint32_t ah[4] = { __float_as_uint(h0), __float_as_uint(h1),
                               __float_as_uint(h2), __float_as_uint(h3) };
            uint32_t al[4] = { __float_as_uint(r0 - h0), __float_as_uint(r1 - h1),
                               __float_as_uint(r2 - h2), __float_as_uint(r3 - h3) };
#pragma unroll
            for (int nj = 0; nj < 4; nj++) {
                mma_tf32(acc[mi][nj], ah, bh[nj][0], bh[nj][1]);
                mma_tf32(acc[mi][nj], ah, bl[nj][0], bl[nj][1]);
                mma_tf32(acc[mi][nj], al, bh[nj][0], bh[nj][1]);
            }
        }
    }

#pragma unroll
    for (int mi = 0; mi < 4; mi++) {
        int r = row0 + wm * 64 + mi * 16 + l4;
        const float* zw0 = nullptr;
        const float* zw1 = nullptr;
        if (ZADD) {
            zw0 = ZW + (size_t)((r     < M) ? z[r]     : 0) * HID;
            zw1 = ZW + (size_t)((r + 8 < M) ? z[r + 8] : 0) * HID;
        }
#pragma unroll
        for (int nj = 0; nj < 4; nj++) {
            int c = wn * 32 + nj * 8 + 2 * lm;
            float v0 = acc[mi][nj][0], v1 = acc[mi][nj][1];
            float v2 = acc[mi][nj][2], v3 = acc[mi][nj][3];
            if (ZADD) {
                v0 += zw0[c]; v1 += zw0[c + 1];
                v2 += zw1[c]; v3 += zw1[c + 1];
            }
            if (RELU) {
                float b0v = bias[c], b1v = bias[c + 1];
                v0 = fmaxf(v0 + b0v, 0.f); v1 = fmaxf(v1 + b1v, 0.f);
                v2 = fmaxf(v2 + b0v, 0.f); v3 = fmaxf(v3 + b1v, 0.f);
            }
            if (r < M)
                *(float2*)(C + (size_t)r * HID + c) = make_float2(v0, v1);
            if (r + 8 < M)
                *(float2*)(C + (size_t)(r + 8) * HID + c) = make_float2(v2, v3);
        }
    }
}

// ---------------- X = tanh(A_norm @ T + b); packed f32x2 FMA -----------------
#define AGG_SMEM ((NODES * HID + EDGES * 2 + 104) * 4)   // 64416 B
__global__ void __launch_bounds__(512) agg_tanh(
    const float* __restrict__ T, const float* __restrict__ bias,
    float* __restrict__ Xout, int g0)
{
    extern __shared__ float sm[];
    float* Ts   = sm;
    int2*  sed  = (int2*)(sm + NODES * HID);
    int*   soff = (int*)(sed + EDGES);

    const int g = g0 + blockIdx.x, tid = threadIdx.x;
    const float* Tg = T + (size_t)g * NODES * HID;

    for (int t = tid; t < NODES * HID / 4; t += 512)
        ((float4*)Ts)[t] = ((const float4*)Tg)[t];
    const int4* egi = (const int4*)(g_edge + (size_t)g * EDGES);
    for (int t = tid; t < EDGES / 2; t += 512)
        ((int4*)sed)[t] = egi[t];
    if (tid <= NODES) soff[tid] = g_off[g * 101 + tid];
    __syncthreads();

    const int lane = tid & 31, warp = tid >> 5;
    const float4 bv = *(const float4*)(bias + lane * 4);

    for (int d = warp; d < NODES; d += 16) {
        int e0 = soff[d], e1 = soff[d + 1];
        unsigned long long aA = 0ull, aB = 0ull;
#pragma unroll 4
        for (int e = e0; e < e1; e++) {
            int2 pe = sed[e];
            ulonglong2 tv = *(const ulonglong2*)&Ts[pe.x * HID + lane * 4];
            unsigned long long w2 = pk2i(pe.y);
            ffma2(aA, w2, tv.x);
            ffma2(aB, w2, tv.y);
        }
        float2 aXY = up2(aA), aZW = up2(aB);
        float4 o;
        o.x = acc_tanh(aXY.x + bv.x);
        o.y = acc_tanh(aXY.y + bv.y);
        o.z = acc_tanh(aZW.x + bv.z);
        o.w = acc_tanh(aZW.y + bv.w);
        *(float4*)(Xout + ((size_t)g * NODES + d) * HID + lane * 4) = o;
    }
}

// ---------------- final part 1: layer3 + sort-pool + conv1/2 -> flat --------
#define FEAT_SMEM_FLOATS 25616
__global__ void __launch_bounds__(256) final_feat(
    const float* __restrict__ W3,  const float* __restrict__ b3,
    const float* __restrict__ cw1, const float* __restrict__ cb1,
    const float* __restrict__ cw2, const float* __restrict__ cb2, int g0)
{
    extern __shared__ float sm[];
    float* W3s  = sm;
    float* cw1s = W3s + 128;
    float* cw2s = cw1s + 6208;
    float* feat = cw2s + 2560;
    float* t3   = feat + 15520;
    float* x3   = t3 + 100;
    float* y1   = x3 + 100;
    float* mmp  = y1 + 640;
    int*   topi = (int*)(mmp + 320);

    const int g = g0 + blockIdx.x, tid = threadIdx.x;
    const float* X2g = g_X2 + (size_t)g * NODES * HID;

    if (tid < 128) W3s[tid] = W3[tid];
    for (int t = tid; t < 16 * 385; t += 256) {
        int c = t / 385, d = t - c * 385;
        cw1s[c * 388 + d] = cw1[t];
    }
    if (tid < 16) {
        cw1s[tid * 388 + 385] = 0.f;
        cw1s[tid * 388 + 386] = 0.f;
        cw1s[tid * 388 + 387] = 0.f;
    }
    for (int t = tid; t < 2560; t += 256) cw2s[t] = cw2[t];
    __syncthreads();

    if (tid < NODES) {
        const float4* xr = (const float4*)(X2g + (size_t)tid * HID);
        const float4* wr = (const float4*)W3s;
        float a = 0.f;
#pragma unroll 8
        for (int k = 0; k < 32; k++) {
            float4 xv = xr[k], wv = wr[k];
            a += xv.x * wv.x + xv.y * wv.y + xv.z * wv.z + xv.w * wv.w;
        }
        t3[tid] = a;
    }
    __syncthreads();

    if (tid < NODES) {
        const int*  offp = g_off + g * 101;
        const int2* ep   = g_edge + (size_t)g * EDGES;
        float a = 0.f;
        int e1 = offp[tid + 1];
        for (int e = offp[tid]; e < e1; e++) {
            int2 pe = ep[e];
            a += __int_as_float(pe.y) * t3[pe.x];
        }
        x3[tid] = acc_tanh(a + b3[0]);
    }
    __syncthreads();

    if (tid < NODES) {
        float v = x3[tid];
        int r = 0;
        for (int j = 0; j < NODES; j++) {
            float u = x3[j];
            r += (u > v) || (u == v && j < tid);
        }
        if (r < KTOP) topi[r] = tid;
    }
    __syncthreads();

    for (int t = tid; t < KTOP * HID; t += 256) {
        int k = t >> 7, d = t & 127;
        int node = topi[k];
        size_t gbase = ((size_t)g * NODES + node) * HID + d;
        feat[k * 388 + d]       = g_X0[gbase];
        feat[k * 388 + 128 + d] = g_X1[gbase];
        feat[k * 388 + 256 + d] = g_X2[gbase];
    }
    if (tid < KTOP) {
        feat[tid * 388 + 384] = x3[topi[tid]];
        feat[tid * 388 + 385] = 0.f;
        feat[tid * 388 + 386] = 0.f;
        feat[tid * 388 + 387] = 0.f;
    }
    __syncthreads();

    for (int o = tid; o < 640; o += 256) {
        int c = o & 15, kp = o >> 4;
        const float4* wr = (const float4*)(cw1s + c * 388);
        const float4* fr = (const float4*)(feat + kp * 388);
        unsigned long long s0 = 0ull, s1 = 0ull;
#pragma unroll 4
        for (int d = 0; d < 97; d++) {
            float4 w4 = wr[d], f4 = fr[d];
            ffma2(s0, pkf2(w4.x, w4.y), pkf2(f4.x, f4.y));
            ffma2(s1, pkf2(w4.z, w4.w), pkf2(f4.z, f4.w));
        }
        float a = cb1[c] + hsum2(s0) + hsum2(s1);
        y1[c * 40 + kp] = fmaxf(a, 0.f);
    }
    __syncthreads();

    for (int t = tid; t < 320; t += 256) {
        int c = t / 20, p = t % 20;
        mmp[t] = fmaxf(y1[c * 40 + 2 * p], y1[c * 40 + 2 * p + 1]);
    }
    __syncthreads();

    for (int t = tid; t < 512; t += 256) {
        int o2 = t >> 4, p = t & 15;
        float a = cb2[o2];
#pragma unroll
        for (int c = 0; c < 16; c++)
#pragma unroll
            for (int u = 0; u < 5; u++)
                a += cw2s[(o2 * 16 + c) * 5 + u] * mmp[c * 20 + p + u];
        g_flat[(size_t)g * 512 + t] = fmaxf(a, 0.f);
    }
}

// ---------------- final part 3: out = rr @ mW2 + mb2 ------------------------
__global__ void __launch_bounds__(256) out_k(
    const float* __restrict__ mW2, const float* __restrict__ mb2,
    float* __restrict__ out, int g0, int gcount)
{
    const int warp = threadIdx.x >> 5, lane = threadIdx.x & 31;
    const int gl = blockIdx.x * 8 + warp;
    if (gl >= gcount) return;
    const int g = g0 + gl;
    float s = 0.f;
#pragma unroll
    for (int q = 0; q < 4; q++) {
        int i = lane + 32 * q;
        s += g_P[(size_t)g * 128 + i] * mW2[i];
    }
    for (int off2 = 16; off2 > 0; off2 >>= 1)
        s += __shfl_down_sync(0xffffffffu, s, off2);
    if (lane == 0) out[g] = s + mb2[0];
}

// ---------------- host ------------------------------------------------------
extern "C" void kernel_launch(void* const* d_in, const int* in_sizes, int n_in,
                              void* d_out, int out_size)
{
    const float* x    = (const float*)d_in[0];
    const int*   z    = (const int*)  d_in[1];
    const int*   ei   = (const int*)  d_in[2];
    const float* ztab = (const float*)d_in[4];
    const float* W0   = (const float*)d_in[5];
    const float* b0   = (const float*)d_in[6];
    const float* W1   = (const float*)d_in[7];
    const float* b1   = (const float*)d_in[8];
    const float* W2   = (const float*)d_in[9];
    const float* b2   = (const float*)d_in[10];
    const float* W3   = (const float*)d_in[11];
    const float* b3   = (const float*)d_in[12];
    const float* cw1  = (const float*)d_in[13];
    const float* cb1  = (const float*)d_in[14];
    const float* cw2  = (const float*)d_in[15];
    const float* cb2  = (const float*)d_in[16];
    const float* mW1  = (const float*)d_in[17];
    const float* mb1  = (const float*)d_in[18];
    const float* mW2  = (const float*)d_in[19];
    const float* mb2  = (const float*)d_in[20];
    float* out = (float*)d_out;

    float *T, *X0, *X1, *X2, *ZW, *Wh, *Wl, *flat, *P;
    cudaGetSymbolAddress((void**)&T,   g_T);
    cudaGetSymbolAddress((void**)&X0,  g_X0);
    cudaGetSymbolAddress((void**)&X1,  g_X1);
    cudaGetSymbolAddress((void**)&X2,  g_X2);
    cudaGetSymbolAddress((void**)&ZW,  g_ZW);
    cudaGetSymbolAddress((void**)&Wh,  g_Wh);
    cudaGetSymbolAddress((void**)&Wl,  g_Wl);
    cudaGetSymbolAddress((void**)&flat, g_flat);
    cudaGetSymbolAddress((void**)&P,   g_P);

    static cudaStream_t s1 = nullptr, s2 = nullptr;
    static cudaEvent_t  eR = nullptr, e1 = nullptr, e2 = nullptr;
    static bool init_done = false;
    if (!init_done) {
        cudaStreamCreateWithFlags(&s1, cudaStreamNonBlocking);
        cudaStreamCreateWithFlags(&s2, cudaStreamNonBlocking);
        cudaEventCreateWithFlags(&eR, cudaEventDisableTiming);
        cudaEventCreateWithFlags(&e1, cudaEventDisableTiming);
        cudaEventCreateWithFlags(&e2, cudaEventDisableTiming);
        cudaFuncSetAttribute((const void*)gemm_tc<128, 0, 0>, cudaFuncAttributeMaxDynamicSharedMemorySize, GEMM_SM);
        cudaFuncSetAttribute((const void*)gemm_tc<128, 0, 1>, cudaFuncAttributeMaxDynamicSharedMemorySize, GEMM_SM);
        cudaFuncSetAttribute((const void*)gemm_tc<512, 1, 0>, cudaFuncAttributeMaxDynamicSharedMemorySize, GEMM_SM);
        cudaFuncSetAttribute((const void*)agg_tanh, cudaFuncAttributeMaxDynamicSharedMemorySize, AGG_SMEM);
        cudaFuncSetAttribute((const void*)final_feat, cudaFuncAttributeMaxDynamicSharedMemorySize, FEAT_SMEM_FLOATS * 4);
        init_done = true;
    }

    const int GEMM_GRID_H = (MH + 127) / 128;     // 391
    const int MLP_GRID_H  = (HALF + 127) / 128;   // 4

    // csr has no dependency on weight prep — start it immediately on both streams
    build_csr<<<HALF, 256, 0, s1>>>(ei, 0);
    build_csr<<<HALF, 256, 0, s2>>>(ei, HALF);

    // root: weight splits + ZW = ztab @ W0_top (overlaps with csr)
    prep_gcn<<<256, 256>>>(W0, W1, W2);
    prep_mlp<<<256, 256>>>(mW1);
    gemm_tc<128, 0, 0><<<8, 256, GEMM_SM>>>(
        ztab, nullptr, nullptr, Wh, Wl, nullptr, ZW, 1000);
    cudaEventRecord(eR, 0);
    cudaStreamWaitEvent(s1, eR, 0);
    cudaStreamWaitEvent(s2, eR, 0);

    // two independent half-pipelines
    for (int h = 0; h < 2; h++) {
        cudaStream_t s = h ? s2 : s1;
        const int g0 = h * HALF;
        const size_t rb = (size_t)g0 * NODES;

        // layer0: T = x @ W0_bot + ZW[z]
        gemm_tc<128, 0, 1><<<GEMM_GRID_H, 256, GEMM_SM, s>>>(
            x + rb * HID, z + rb, ZW, Wh + 128 * 128, Wl + 128 * 128,
            nullptr, T + rb * HID, MH);
        agg_tanh<<<HALF, 512, AGG_SMEM, s>>>(T, b0, X0, g0);

        gemm_tc<128, 0, 0><<<GEMM_GRID_H, 256, GEMM_SM, s>>>(
            X0 + rb * HID, nullptr, nullptr,
            Wh + 256 * 128, Wl + 256 * 128, nullptr, T + rb * HID, MH);
        agg_tanh<<<HALF, 512, AGG_SMEM, s>>>(T, b1, X1, g0);

        gemm_tc<128, 0, 0><<<GEMM_GRID_H, 256, GEMM_SM, s>>>(
            X1 + rb * HID, nullptr, nullptr,
            Wh + 384 * 128, Wl + 384 * 128, nullptr, T + rb * HID, MH);
        agg_tanh<<<HALF, 512, AGG_SMEM, s>>>(T, b2, X2, g0);

        final_feat<<<HALF, 256, FEAT_SMEM_FLOATS * 4, s>>>(
            W3, b3, cw1, cb1, cw2, cb2, g0);

        gemm_tc<512, 1, 0><<<MLP_GRID_H, 256, GEMM_SM, s>>>(
            flat + (size_t)g0 * 512, nullptr, nullptr,
            Wh + 512 * 128, Wl + 512 * 128, mb1, P + (size_t)g0 * 128, HALF);

        out_k<<<(HALF + 7) / 8, 256, 0, s>>>(mW2, mb2, out, g0, HALF);
    }

    // join halves back onto the capture stream
    cudaEventRecord(e1, s1);
    cudaEventRecord(e2, s2);
    cudaStreamWaitEvent(0, e1, 0);
    cudaStreamWaitEvent(0, e2, 0);
}

// round 17
// speedup vs baseline: 1.1037x; 1.0263x over previous
#include <cuda_runtime.h>
#include <cstdint>

#define NG    1000
#define NODES 100
#define EDGES 1600
#define NTOT  100000
#define ETOT  1600000
#define HID   128
#define KTOP  40
#define HALF  500
#define MH    (HALF * NODES)

// ---------------- scratch (device globals; no runtime allocation) ----------
__device__ float g_T  [(size_t)NTOT * HID];
__device__ float g_X0 [(size_t)NTOT * HID];
__device__ float g_X1 [(size_t)NTOT * HID];
__device__ float g_X2 [(size_t)NTOT * HID];
__device__ float g_ZW [1000 * HID];
__device__ float g_Wh [1024 * 128];
__device__ float g_Wl [1024 * 128];
__device__ float g_flat[(size_t)NG * 512];
__device__ float g_P  [(size_t)NG * 128];
__device__ int   g_off [NG * 101];
__device__ int2  g_edge[ETOT];

// ---------------- helpers ---------------------------------------------------
__device__ __forceinline__ float acc_tanh(float x) {
    float xc = fminf(fmaxf(x, -10.f), 10.f);
    float e  = __expf(2.f * xc);
    return (e - 1.f) / (e + 1.f);
}
__device__ __forceinline__ float f2tf32f(float x) {
    uint32_t r;
    asm("cvt.rna.tf32.f32 %0, %1;" : "=r"(r) : "f"(x));
    return __uint_as_float(r);
}
__device__ __forceinline__ void mma_tf32(float c[4], const uint32_t a[4],
                                         const uint32_t b0, const uint32_t b1) {
    asm volatile(
        "mma.sync.aligned.m16n8k8.row.col.f32.tf32.tf32.f32 "
        "{%0,%1,%2,%3}, {%4,%5,%6,%7}, {%8,%9}, {%0,%1,%2,%3};\n"
        : "+f"(c[0]), "+f"(c[1]), "+f"(c[2]), "+f"(c[3])
        : "r"(a[0]), "r"(a[1]), "r"(a[2]), "r"(a[3]), "r"(b0), "r"(b1));
}
__device__ __forceinline__ uint32_t smem_u32(const void* p) {
    return (uint32_t)__cvta_generic_to_shared(p);
}
#define CP16(dst, src) \
    asm volatile("cp.async.cg.shared.global [%0], [%1], 16;\n" :: "r"(dst), "l"(src))
#define CPCOMMIT() asm volatile("cp.async.commit_group;\n" ::: "memory")
#define CPWAIT2()  asm volatile("cp.async.wait_group 2;\n" ::: "memory")

__device__ __forceinline__ unsigned long long pkf2(float a, float b) {
    unsigned long long r;
    asm("mov.b64 %0, {%1, %2};" : "=l"(r) : "r"(__float_as_int(a)), "r"(__float_as_int(b)));
    return r;
}
__device__ __forceinline__ unsigned long long pk2i(int x) {
    unsigned long long r;
    asm("mov.b64 %0, {%1, %1};" : "=l"(r) : "r"(x));
    return r;
}
__device__ __forceinline__ void ffma2(unsigned long long& d,
                                      unsigned long long a, unsigned long long b) {
    asm("fma.rn.f32x2 %0, %1, %2, %3;" : "=l"(d) : "l"(a), "l"(b), "l"(d));
}
__device__ __forceinline__ float hsum2(unsigned long long u) {
    int lo, hi;
    asm("mov.b64 {%0, %1}, %2;" : "=r"(lo), "=r"(hi) : "l"(u));
    return __int_as_float(lo) + __int_as_float(hi);
}
__device__ __forceinline__ float2 up2(unsigned long long u) {
    int lo, hi;
    asm("mov.b64 {%0, %1}, %2;" : "=r"(lo), "=r"(hi) : "l"(u));
    return make_float2(__int_as_float(lo), __int_as_float(hi));
}

// ---------------- prep: pre-split ALL weights into hi/lo (one launch) -------
// rows [0,128)=W0_top, [128,256)=W0_bot, [256,384)=W1, [384,512)=W2, [512,1024)=mW1
__global__ void __launch_bounds__(256) prep_w(
    const float* __restrict__ W0, const float* __restrict__ W1,
    const float* __restrict__ W2, const float* __restrict__ mW1)
{
    int t = blockIdx.x * 256 + threadIdx.x;
    if (t >= 1024 * 128) return;
    int row = t >> 7, col = t & 127;
    float v;
    if (row < 256)      v = W0[row * 128 + col];
    else if (row < 384) v = W1[(row - 256) * 128 + col];
    else if (row < 512) v = W2[(row - 384) * 128 + col];
    else                v = mW1[(size_t)(row - 512) * 128 + col];
    float h = f2tf32f(v);
    g_Wh[t] = h;
    g_Wl[t] = v - h;
}

// ---------------- one-pass deterministic CSR --------------------------------
__global__ void __launch_bounds__(256) build_csr(const int* __restrict__ ei, int g0)
{
    __shared__ int2  sedge[EDGES];
    __shared__ int   hist [8][104];
    __shared__ int   cbase[8][104];
    __shared__ int   deg  [NODES];
    __shared__ float dinv [NODES];
    __shared__ int   offs [NODES + 1];

    const int g = g0 + blockIdx.x, tid = threadIdx.x;
    const int lane = tid & 31, warp = tid >> 5;
    const int base = g * NODES;
    const int* srce = ei + (size_t)g * EDGES;
    const int* dste = ei + (size_t)ETOT + (size_t)g * EDGES;

    for (int t = tid; t < 8 * 104; t += 256) ((int*)hist)[t] = 0;
    for (int e = tid; e < EDGES; e += 256)
        sedge[e] = make_int2(srce[e] - base, dste[e] - base);
    __syncthreads();

    const int cbeg = warp * 200;
    for (int j = lane; j < 200; j += 32)
        atomicAdd(&hist[warp][sedge[cbeg + j].y], 1);
    __syncthreads();

    if (tid < NODES) {
        int s = 0;
#pragma unroll
        for (int w = 0; w < 8; w++) s += hist[w][tid];
        deg[tid] = s;
        dinv[tid] = s > 0 ? rsqrtf((float)s) : 0.f;
    }
    __syncthreads();
    if (tid == 0) {
        int acc = 0;
        for (int i = 0; i < NODES; i++) { offs[i] = acc; acc += deg[i]; }
        offs[NODES] = acc;
    }
    __syncthreads();
    if (tid < NODES) {
        int run = offs[tid];
#pragma unroll
        for (int w = 0; w < 8; w++) {
            cbase[w][tid] = run;
            run += hist[w][tid];
            hist[w][tid] = 0;
        }
    }
    if (tid <= NODES) g_off[g * 101 + tid] = offs[tid];
    __syncthreads();

    const size_t gb = (size_t)g * EDGES;
    for (int j0 = 0; j0 < 200; j0 += 32) {
        int j = j0 + lane;
        bool act = j < 200;
        unsigned amask = __ballot_sync(0xffffffffu, act);
        if (act) {
            int2 sd = sedge[cbeg + j];
            unsigned mm = __match_any_sync(amask, sd.y);
            unsigned below = mm & ((1u << lane) - 1);
            int c = hist[warp][sd.y];
            __syncwarp(amask);
            g_edge[gb + cbase[warp][sd.y] + c + __popc(below)] =
                make_int2(sd.x, __float_as_int(dinv[sd.x] * dinv[sd.y]));
            if (below == 0)
                hist[warp][sd.y] = c + __popc(mm);
        }
        __syncwarp();
    }
}

// ---------------- tensor-core 3xTF32 GEMM -----------------------------------
#define B_SLICE 2112
#define A_SLICE 1024
#define GEMM_SM ((4 * A_SLICE + 4 * B_SLICE) * 4)   // 50176 B

template <int K, int RELU, int ZADD>
__global__ void __launch_bounds__(256, 2) gemm_tc(
    const float* __restrict__ Aa, const int* __restrict__ z,
    const float* __restrict__ ZW,
    const float* __restrict__ Wh, const float* __restrict__ Wl,
    const float* __restrict__ bias, float* __restrict__ C, int M)
{
    extern __shared__ float sm[];
    float* As = sm;
    float* Bs = sm + 4 * A_SLICE;

    const int tid = threadIdx.x;
    const int lane = tid & 31, wid = tid >> 5;
    const int wm = wid & 1, wn = wid >> 1;
    const int l4 = lane >> 2, lm = lane & 3;
    const int row0 = blockIdx.x * 128;

    const int arow = tid >> 1, ahalf = (tid & 1) * 4;
    const int bk = tid >> 5, bn4 = (tid & 31) * 4;

    const int gr = row0 + arow;
    const int grc = gr < M ? gr : (M - 1);
    const float* aptr = Aa + (size_t)grc * K;
    const float* bptrH = Wh + (size_t)bk * HID + bn4;
    const float* bptrL = Wl + (size_t)bk * HID + bn4;
    const uint32_t adst = smem_u32(As + arow * 8 + ahalf);
    const uint32_t bdst = smem_u32(Bs + bk * 132 + bn4);

    const int S = K / 8;

    auto issue = [&](int s) {
        const int buf = s & 3;
        CP16(adst + buf * (A_SLICE * 4), aptr + s * 8 + ahalf);
        CP16(bdst + buf * (B_SLICE * 4), bptrH + (size_t)s * 8 * HID);
        CP16(bdst + buf * (B_SLICE * 4) + 4224, bptrL + (size_t)s * 8 * HID);
        CPCOMMIT();
    };

    float acc[4][4][4];
#pragma unroll
    for (int mi = 0; mi < 4; mi++)
#pragma unroll
        for (int nj = 0; nj < 4; nj++)
#pragma unroll
            for (int q = 0; q < 4; q++) acc[mi][nj][q] = 0.f;

    issue(0); issue(1); issue(2);

#pragma unroll 1
    for (int s = 0; s < S; s++) {
        CPWAIT2();
        __syncthreads();
        if (s + 3 < S) issue(s + 3);

        const float* A0  = As + (s & 3) * A_SLICE;
        const float* B0h = Bs + (s & 3) * B_SLICE;
        const float* B0l = B0h + 1056;

        uint32_t bh[4][2], bl[4][2];
#pragma unroll
        for (int nj = 0; nj < 4; nj++) {
            int n = wn * 32 + nj * 8 + l4;
            bh[nj][0] = __float_as_uint(B0h[lm * 132 + n]);
            bh[nj][1] = __float_as_uint(B0h[(lm + 4) * 132 + n]);
            bl[nj][0] = __float_as_uint(B0l[lm * 132 + n]);
            bl[nj][1] = __float_as_uint(B0l[(lm + 4) * 132 + n]);
        }
#pragma unroll
        for (int mi = 0; mi < 4; mi++) {
            int r = (wm * 4 + mi) * 16 + l4;
            float r0 = A0[r * 8 + lm];
            float r1 = A0[(r + 8) * 8 + lm];
            float r2 = A0[r * 8 + lm + 4];
            float r3 = A0[(r + 8) * 8 + lm + 4];
            float h0 = f2tf32f(r0), h1 = f2tf32f(r1);
            float h2 = f2tf32f(r2), h3 = f2tf32f(r3);
            uint32_t ah[4] = { __float_as_uint(h0), __float_as_uint(h1),
                               __float_as_uint(h2), __float_as_uint(h3) };
            uint32_t al[4] = { __float_as_uint(r0 - h0), __float_as_uint(r1 - h1),
                               __float_as_uint(r2 - h2), __float_as_uint(r3 - h3) };
#pragma unroll
            for (int nj = 0; nj < 4; nj++) {
                mma_tf32(acc[mi][nj], ah, bh[nj][0], bh[nj][1]);
                mma_tf32(acc[mi][nj], ah, bl[nj][0], bl[nj][1]);
                mma_tf32(acc[mi][nj], al, bh[nj][0], bh[nj][1]);
            }
        }
    }

#pragma unroll
    for (int mi = 0; mi < 4; mi++) {
        int r = row0 + wm * 64 + mi * 16 + l4;
        const float* zw0 = nullptr;
        const float* zw1 = nullptr;
        if (ZADD) {
            zw0 = ZW + (size_t)((r     < M) ? z[r]     : 0) * HID;
            zw1 = ZW + (size_t)((r + 8 < M) ? z[r + 8] : 0) * HID;
        }
#pragma unroll
        for (int nj = 0; nj < 4; nj++) {
            int c = wn * 32 + nj * 8 + 2 * lm;
            float v0 = acc[mi][nj][0], v1 = acc[mi][nj][1];
            float v2 = acc[mi][nj][2], v3 = acc[mi][nj][3];
            if (ZADD) {
                v0 += zw0[c]; v1 += zw0[c + 1];
                v2 += zw1[c]; v3 += zw1[c + 1];
            }
            if (RELU) {
                float b0v = bias[c], b1v = bias[c + 1];
                v0 = fmaxf(v0 + b0v, 0.f); v1 = fmaxf(v1 + b1v, 0.f);
                v2 = fmaxf(v2 + b0v, 0.f); v3 = fmaxf(v3 + b1v, 0.f);
            }
            if (r < M)
                *(float2*)(C + (size_t)r * HID + c) = make_float2(v0, v1);
            if (r + 8 < M)
                *(float2*)(C + (size_t)(r + 8) * HID + c) = make_float2(v2, v3);
        }
    }
}

// ---------------- X = tanh(A_norm @ T + b); packed f32x2 FMA -----------------
#define AGG_SMEM ((NODES * HID + EDGES * 2 + 104) * 4)   // 64416 B
__global__ void __launch_bounds__(512) agg_tanh(
    const float* __restrict__ T, const float* __restrict__ bias,
    float* __restrict__ Xout, int g0)
{
    extern __shared__ float sm[];
    float* Ts   = sm;
    int2*  sed  = (int2*)(sm + NODES * HID);
    int*   soff = (int*)(sed + EDGES);

    const int g = g0 + blockIdx.x, tid = threadIdx.x;
    const float* Tg = T + (size_t)g * NODES * HID;

    for (int t = tid; t < NODES * HID / 4; t += 512)
        ((float4*)Ts)[t] = ((const float4*)Tg)[t];
    const int4* egi = (const int4*)(g_edge + (size_t)g * EDGES);
    for (int t = tid; t < EDGES / 2; t += 512)
        ((int4*)sed)[t] = egi[t];
    if (tid <= NODES) soff[tid] = g_off[g * 101 + tid];
    __syncthreads();

    const int lane = tid & 31, warp = tid >> 5;
    const float4 bv = *(const float4*)(bias + lane * 4);

    for (int d = warp; d < NODES; d += 16) {
        int e0 = soff[d], e1 = soff[d + 1];
        unsigned long long aA = 0ull, aB = 0ull;
#pragma unroll 4
        for (int e = e0; e < e1; e++) {
            int2 pe = sed[e];
            ulonglong2 tv = *(const ulonglong2*)&Ts[pe.x * HID + lane * 4];
            unsigned long long w2 = pk2i(pe.y);
            ffma2(aA, w2, tv.x);
            ffma2(aB, w2, tv.y);
        }
        float2 aXY = up2(aA), aZW = up2(aB);
        float4 o;
        o.x = acc_tanh(aXY.x + bv.x);
        o.y = acc_tanh(aXY.y + bv.y);
        o.z = acc_tanh(aZW.x + bv.z);
        o.w = acc_tanh(aZW.y + bv.w);
        *(float4*)(Xout + ((size_t)g * NODES + d) * HID + lane * 4) = o;
    }
}

// ---------------- final part 1: layer3 + sort-pool + conv1/2 -> flat --------
// 512 threads: conv1/gather/conv2 work per thread halves vs 256.
#define FEAT_SMEM_FLOATS 25616
__global__ void __launch_bounds__(512) final_feat(
    const float* __restrict__ W3,  const float* __restrict__ b3,
    const float* __restrict__ cw1, const float* __restrict__ cb1,
    const float* __restrict__ cw2, const float* __restrict__ cb2, int g0)
{
    extern __shared__ float sm[];
    float* W3s  = sm;
    float* cw1s = W3s + 128;
    float* cw2s = cw1s + 6208;
    float* feat = cw2s + 2560;
    float* t3   = feat + 15520;
    float* x3   = t3 + 100;
    float* y1   = x3 + 100;
    float* mmp  = y1 + 640;
    int*   topi = (int*)(mmp + 320);

    const int g = g0 + blockIdx.x, tid = threadIdx.x;
    const float* X2g = g_X2 + (size_t)g * NODES * HID;

    if (tid < 128) W3s[tid] = W3[tid];
    for (int t = tid; t < 16 * 385; t += 512) {
        int c = t / 385, d = t - c * 385;
        cw1s[c * 388 + d] = cw1[t];
    }
    if (tid < 16) {
        cw1s[tid * 388 + 385] = 0.f;
        cw1s[tid * 388 + 386] = 0.f;
        cw1s[tid * 388 + 387] = 0.f;
    }
    for (int t = tid; t < 2560; t += 512) cw2s[t] = cw2[t];
    __syncthreads();

    if (tid < NODES) {
        const float4* xr = (const float4*)(X2g + (size_t)tid * HID);
        const float4* wr = (const float4*)W3s;
        float a = 0.f;
#pragma unroll 8
        for (int k = 0; k < 32; k++) {
            float4 xv = xr[k], wv = wr[k];
            a += xv.x * wv.x + xv.y * wv.y + xv.z * wv.z + xv.w * wv.w;
        }
        t3[tid] = a;
    }
    __syncthreads();

    if (tid < NODES) {
        const int*  offp = g_off + g * 101;
        const int2* ep   = g_edge + (size_t)g * EDGES;
        float a = 0.f;
        int e1 = offp[tid + 1];
        for (int e = offp[tid]; e < e1; e++) {
            int2 pe = ep[e];
            a += __int_as_float(pe.y) * t3[pe.x];
        }
        x3[tid] = acc_tanh(a + b3[0]);
    }
    __syncthreads();

    if (tid < NODES) {
        float v = x3[tid];
        int r = 0;
        for (int j = 0; j < NODES; j++) {
            float u = x3[j];
            r += (u > v) || (u == v && j < tid);
        }
        if (r < KTOP) topi[r] = tid;
    }
    __syncthreads();

    for (int t = tid; t < KTOP * HID; t += 512) {
        int k = t >> 7, d = t & 127;
        int node = topi[k];
        size_t gbase = ((size_t)g * NODES + node) * HID + d;
        feat[k * 388 + d]       = g_X0[gbase];
        feat[k * 388 + 128 + d] = g_X1[gbase];
        feat[k * 388 + 256 + d] = g_X2[gbase];
    }
    if (tid < KTOP) {
        feat[tid * 388 + 384] = x3[topi[tid]];
        feat[tid * 388 + 385] = 0.f;
        feat[tid * 388 + 386] = 0.f;
        feat[tid * 388 + 387] = 0.f;
    }
    __syncthreads();

    for (int o = tid; o < 640; o += 512) {
        int c = o & 15, kp = o >> 4;
        const float4* wr = (const float4*)(cw1s + c * 388);
        const float4* fr = (const float4*)(feat + kp * 388);
        unsigned long long s0 = 0ull, s1 = 0ull;
#pragma unroll 4
        for (int d = 0; d < 97; d++) {
            float4 w4 = wr[d], f4 = fr[d];
            ffma2(s0, pkf2(w4.x, w4.y), pkf2(f4.x, f4.y));
            ffma2(s1, pkf2(w4.z, w4.w), pkf2(f4.z, f4.w));
        }
        float a = cb1[c] + hsum2(s0) + hsum2(s1);
        y1[c * 40 + kp] = fmaxf(a, 0.f);
    }
    __syncthreads();

    for (int t = tid; t < 320; t += 512) {
        int c = t / 20, p = t % 20;
        mmp[t] = fmaxf(y1[c * 40 + 2 * p], y1[c * 40 + 2 * p + 1]);
    }
    __syncthreads();

    if (tid < 512) {
        int t = tid;
        int o2 = t >> 4, p = t & 15;
        float a = cb2[o2];
#pragma unroll
        for (int c = 0; c < 16; c++)
#pragma unroll
            for (int u = 0; u < 5; u++)
                a += cw2s[(o2 * 16 + c) * 5 + u] * mmp[c * 20 + p + u];
        g_flat[(size_t)g * 512 + t] = fmaxf(a, 0.f);
    }
}

// ---------------- final part 3: out = rr @ mW2 + mb2 ------------------------
__global__ void __launch_bounds__(256) out_k(
    const float* __restrict__ mW2, const float* __restrict__ mb2,
    float* __restrict__ out, int g0, int gcount)
{
    const int warp = threadIdx.x >> 5, lane = threadIdx.x & 31;
    const int gl = blockIdx.x * 8 + warp;
    if (gl >= gcount) return;
    const int g = g0 + gl;
    float s = 0.f;
#pragma unroll
    for (int q = 0; q < 4; q++) {
        int i = lane + 32 * q;
        s += g_P[(size_t)g * 128 + i] * mW2[i];
    }
    for (int off2 = 16; off2 > 0; off2 >>= 1)
        s += __shfl_down_sync(0xffffffffu, s, off2);
    if (lane == 0) out[g] = s + mb2[0];
}

// ---------------- host ------------------------------------------------------
extern "C" void kernel_launch(void* const* d_in, const int* in_sizes, int n_in,
                              void* d_out, int out_size)
{
    const float* x    = (const float*)d_in[0];
    const int*   z    = (const int*)  d_in[1];
    const int*   ei   = (const int*)  d_in[2];
    const float* ztab = (const float*)d_in[4];
    const float* W0   = (const float*)d_in[5];
    const float* b0   = (const float*)d_in[6];
    const float* W1   = (const float*)d_in[7];
    const float* b1   = (const float*)d_in[8];
    const float* W2   = (const float*)d_in[9];
    const float* b2   = (const float*)d_in[10];
    const float* W3   = (const float*)d_in[11];
    const float* b3   = (const float*)d_in[12];
    const float* cw1  = (const float*)d_in[13];
    const float* cb1  = (const float*)d_in[14];
    const float* cw2  = (const float*)d_in[15];
    const float* cb2  = (const float*)d_in[16];
    const float* mW1  = (const float*)d_in[17];
    const float* mb1  = (const float*)d_in[18];
    const float* mW2  = (const float*)d_in[19];
    const float* mb2  = (const float*)d_in[20];
    float* out = (float*)d_out;

    float *T, *X0, *X1, *X2, *ZW, *Wh, *Wl, *flat, *P;
    cudaGetSymbolAddress((void**)&T,   g_T);
    cudaGetSymbolAddress((void**)&X0,  g_X0);
    cudaGetSymbolAddress((void**)&X1,  g_X1);
    cudaGetSymbolAddress((void**)&X2,  g_X2);
    cudaGetSymbolAddress((void**)&ZW,  g_ZW);
    cudaGetSymbolAddress((void**)&Wh,  g_Wh);
    cudaGetSymbolAddress((void**)&Wl,  g_Wl);
    cudaGetSymbolAddress((void**)&flat, g_flat);
    cudaGetSymbolAddress((void**)&P,   g_P);

    static cudaStream_t s1 = nullptr, s2 = nullptr;
    static cudaEvent_t  eR = nullptr, e1 = nullptr, e2 = nullptr;
    static bool init_done = false;
    if (!init_done) {
        cudaStreamCreateWithFlags(&s1, cudaStreamNonBlocking);
        cudaStreamCreateWithFlags(&s2, cudaStreamNonBlocking);
        cudaEventCreateWithFlags(&eR, cudaEventDisableTiming);
        cudaEventCreateWithFlags(&e1, cudaEventDisableTiming);
        cudaEventCreateWithFlags(&e2, cudaEventDisableTiming);
        cudaFuncSetAttribute((const void*)gemm_tc<128, 0, 0>, cudaFuncAttributeMaxDynamicSharedMemorySize, GEMM_SM);
        cudaFuncSetAttribute((const void*)gemm_tc<128, 0, 1>, cudaFuncAttributeMaxDynamicSharedMemorySize, GEMM_SM);
        cudaFuncSetAttribute((const void*)gemm_tc<512, 1, 0>, cudaFuncAttributeMaxDynamicSharedMemorySize, GEMM_SM);
        cudaFuncSetAttribute((const void*)agg_tanh, cudaFuncAttributeMaxDynamicSharedMemorySize, AGG_SMEM);
        cudaFuncSetAttribute((const void*)final_feat, cudaFuncAttributeMaxDynamicSharedMemorySize, FEAT_SMEM_FLOATS * 4);
        init_done = true;
    }

    const int GEMM_GRID_H = (MH + 127) / 128;     // 391
    const int MLP_GRID_H  = (HALF + 127) / 128;   // 4

    // csr has no dependency on weight prep — start it immediately on both streams
    build_csr<<<HALF, 256, 0, s1>>>(ei, 0);
    build_csr<<<HALF, 256, 0, s2>>>(ei, HALF);

    // root: weight split + ZW = ztab @ W0_top (overlaps with csr)
    prep_w<<<512, 256>>>(W0, W1, W2, mW1);
    gemm_tc<128, 0, 0><<<8, 256, GEMM_SM>>>(
        ztab, nullptr, nullptr, Wh, Wl, nullptr, ZW, 1000);
    cudaEventRecord(eR, 0);
    cudaStreamWaitEvent(s1, eR, 0);
    cudaStreamWaitEvent(s2, eR, 0);

    // two independent half-pipelines
    for (int h = 0; h < 2; h++) {
        cudaStream_t s = h ? s2 : s1;
        const int g0 = h * HALF;
        const size_t rb = (size_t)g0 * NODES;

        // layer0: T = x @ W0_bot + ZW[z]
        gemm_tc<128, 0, 1><<<GEMM_GRID_H, 256, GEMM_SM, s>>>(
            x + rb * HID, z + rb, ZW, Wh + 128 * 128, Wl + 128 * 128,
            nullptr, T + rb * HID, MH);
        agg_tanh<<<HALF, 512, AGG_SMEM, s>>>(T, b0, X0, g0);

        gemm_tc<128, 0, 0><<<GEMM_GRID_H, 256, GEMM_SM, s>>>(
            X0 + rb * HID, nullptr, nullptr,
            Wh + 256 * 128, Wl + 256 * 128, nullptr, T + rb * HID, MH);
        agg_tanh<<<HALF, 512, AGG_SMEM, s>>>(T, b1, X1, g0);

        gemm_tc<128, 0, 0><<<GEMM_GRID_H, 256, GEMM_SM, s>>>(
            X1 + rb * HID, nullptr, nullptr,
            Wh + 384 * 128, Wl + 384 * 128, nullptr, T + rb * HID, MH);
        agg_tanh<<<HALF, 512, AGG_SMEM, s>>>(T, b2, X2, g0);

        final_feat<<<HALF, 512, FEAT_SMEM_FLOATS * 4, s>>>(
            W3, b3, cw1, cb1, cw2, cb2, g0);

        gemm_tc<512, 1, 0><<<MLP_GRID_H, 256, GEMM_SM, s>>>(
            flat + (size_t)g0 * 512, nullptr, nullptr,
            Wh + 512 * 128, Wl + 512 * 128, mb1, P + (size_t)g0 * 128, HALF);

        out_k<<<(HALF + 7) / 8, 256, 0, s>>>(mW2, mb2, out, g0, HALF);
    }

    // join halves back onto the capture stream
    cudaEventRecord(e1, s1);
    cudaEventRecord(e2, s2);
    cudaStreamWaitEvent(0, e1, 0);
    cudaStreamWaitEvent(0, e2, 0);
}